// round 14
// baseline (speedup 1.0000x reference)
#include <cuda_runtime.h>
#include <cuda_bf16.h>
#include <float.h>
#include <cstdint>

// Problem constants
#define V_   32000
#define C_   1024
#define H_   16
#define L_   8
#define F_   4096
#define B_   2
#define T_   2048
#define D_   64
#define BT_  (B_*T_)
#define QKV_ (3*C_)

// ===========================================================================
// helpers
// ===========================================================================
__device__ __forceinline__ uint32_t smem_u32(const void* p) {
    uint32_t a;
    asm("{ .reg .u64 t; cvta.to.shared.u64 t, %1; cvt.u32.u64 %0, t; }"
        : "=r"(a) : "l"(p));
    return a;
}

#define CP_ASYNC16(saddr, gptr) \
    asm volatile("cp.async.cg.shared.global [%0], [%1], 16;" \
                 :: "r"(saddr), "l"(gptr) : "memory")
#define CP_COMMIT() asm volatile("cp.async.commit_group;" ::: "memory")
#define CP_WAIT1()  asm volatile("cp.async.wait_group 1;" ::: "memory")
#define CP_WAIT0()  asm volatile("cp.async.wait_group 0;" ::: "memory")

__device__ __forceinline__ void ldm_x4(uint32_t addr, uint32_t& r0, uint32_t& r1,
                                       uint32_t& r2, uint32_t& r3) {
    asm volatile("ldmatrix.sync.aligned.m8n8.x4.shared.b16 {%0,%1,%2,%3}, [%4];"
                 : "=r"(r0), "=r"(r1), "=r"(r2), "=r"(r3) : "r"(addr));
}

__device__ __forceinline__ void mma_bf16(float& d0, float& d1, float& d2, float& d3,
                                         uint32_t a0, uint32_t a1, uint32_t a2, uint32_t a3,
                                         uint32_t b0, uint32_t b1) {
    asm volatile(
        "mma.sync.aligned.m16n8k16.row.col.f32.bf16.bf16.f32 "
        "{%0,%1,%2,%3}, {%4,%5,%6,%7}, {%8,%9}, {%0,%1,%2,%3};"
        : "+f"(d0), "+f"(d1), "+f"(d2), "+f"(d3)
        : "r"(a0), "r"(a1), "r"(a2), "r"(a3), "r"(b0), "r"(b1));
}

// bf16 hi/lo split helpers
__device__ __forceinline__ void split1(float v, __nv_bfloat16& h, __nv_bfloat16& l) {
    h = __float2bfloat16(v);
    l = __float2bfloat16(v - __bfloat162float(h));
}
__device__ __forceinline__ void split2_store(float x, float y,
                                             __nv_bfloat16* ph, __nv_bfloat16* pl) {
    __nv_bfloat16 h0, h1, l0, l1;
    split1(x, h0, l0); split1(y, h1, l1);
    __nv_bfloat162 H; H.x = h0; H.y = h1;
    __nv_bfloat162 L; L.x = l0; L.y = l1;
    *(__nv_bfloat162*)ph = H;
    *(__nv_bfloat162*)pl = L;
}
__device__ __forceinline__ void split4_store(float4 v, __nv_bfloat16* ph, __nv_bfloat16* pl) {
    split2_store(v.x, v.y, ph, pl);
    split2_store(v.z, v.w, ph + 2, pl + 2);
}
__device__ __forceinline__ void pack_split(float x, float y, uint32_t& hi, uint32_t& lo) {
    __nv_bfloat16 hx, lx, hy, ly;
    split1(x, hx, lx); split1(y, hy, ly);
    __nv_bfloat162 Hh; Hh.x = hx; Hh.y = hy;
    __nv_bfloat162 Ll; Ll.x = lx; Ll.y = ly;
    hi = *reinterpret_cast<uint32_t*>(&Hh);
    lo = *reinterpret_cast<uint32_t*>(&Ll);
}

// ===========================================================================
// Scratch
// ===========================================================================
__device__ float g_x  [BT_ * C_];
__device__ float g_xf [B_ * C_];
__device__ float g_bqkv[L_ * QKV_];

__device__ __nv_bfloat16 g_h_h  [BT_ * C_];
__device__ __nv_bfloat16 g_h_l  [BT_ * C_];
__device__ __nv_bfloat16 g_qkvh [(size_t)BT_ * QKV_];
__device__ __nv_bfloat16 g_qkvl [(size_t)BT_ * QKV_];
__device__ __nv_bfloat16 g_vth  [B_ * H_ * D_ * T_];
__device__ __nv_bfloat16 g_vtl  [B_ * H_ * D_ * T_];
__device__ __nv_bfloat16 g_ao_h [BT_ * C_];
__device__ __nv_bfloat16 g_ao_l [BT_ * C_];
__device__ __nv_bfloat16 g_hid_h[BT_ * F_];
__device__ __nv_bfloat16 g_hid_l[BT_ * F_];

__device__ __nv_bfloat16 g_wqkvT_h[(size_t)L_ * QKV_ * C_];
__device__ __nv_bfloat16 g_wqkvT_l[(size_t)L_ * QKV_ * C_];
__device__ __nv_bfloat16 g_woT_h[L_ * C_ * C_];
__device__ __nv_bfloat16 g_woT_l[L_ * C_ * C_];
__device__ __nv_bfloat16 g_w1T_h[L_ * C_ * F_];
__device__ __nv_bfloat16 g_w1T_l[L_ * C_ * F_];
__device__ __nv_bfloat16 g_w2T_h[L_ * F_ * C_];
__device__ __nv_bfloat16 g_w2T_l[L_ * F_ * C_];

// ===========================================================================
// Embedding (+ QKV bias concat)
// ===========================================================================
__global__ void embed_kernel(const int* __restrict__ idx,
                             const float* __restrict__ emb,
                             const float* __restrict__ pos,
                             const float* __restrict__ bq,
                             const float* __restrict__ bk,
                             const float* __restrict__ bv,
                             float* __restrict__ x,
                             float* __restrict__ bqkv) {
    int row = blockIdx.x;
    int t   = row % T_;
    int tok = idx[row];
    int c   = threadIdx.x * 4;
    float4 e = *(const float4*)(emb + (size_t)tok * C_ + c);
    float4 p = *(const float4*)(pos + (size_t)t   * C_ + c);
    float4 o;
    o.x = e.x + p.x; o.y = e.y + p.y; o.z = e.z + p.z; o.w = e.w + p.w;
    *(float4*)(x + (size_t)row * C_ + c) = o;

    if (blockIdx.x < (L_ * QKV_) / 256) {
        int i = blockIdx.x * 256 + threadIdx.x;
        int layer = i / QKV_;
        int col   = i % QKV_;
        float v;
        if (col < C_)           v = bq[layer * C_ + col];
        else if (col < 2 * C_)  v = bk[layer * C_ + col - C_];
        else                    v = bv[layer * C_ + col - 2 * C_];
        bqkv[i] = v;
    }
}

// ===========================================================================
// Weight transposes + bf16 split — 3 launches (R8 config).
// ===========================================================================
__global__ void transpose_split_kernel(const float* __restrict__ in,
                                       __nv_bfloat16* __restrict__ oh,
                                       __nv_bfloat16* __restrict__ ol,
                                       int K, int N, size_t out_lstride) {
    __shared__ float t[32][33];
    const float* inl = in + (size_t)blockIdx.z * K * N;
    const size_t obase = (size_t)blockIdx.z * out_lstride;
    const int k0 = blockIdx.y * 32;
    const int n0 = blockIdx.x * 32;
    #pragma unroll
    for (int j = 0; j < 4; j++) {
        int k = k0 + threadIdx.y + j * 8;
        t[threadIdx.y + j * 8][threadIdx.x] = inl[(size_t)k * N + n0 + threadIdx.x];
    }
    __syncthreads();
    #pragma unroll
    for (int j = 0; j < 4; j++) {
        int n = n0 + threadIdx.y + j * 8;
        float v = t[threadIdx.x][threadIdx.y + j * 8];
        __nv_bfloat16 h, l;
        split1(v, h, l);
        size_t off = obase + (size_t)n * K + k0 + threadIdx.x;
        oh[off] = h;
        ol[off] = l;
    }
}

__global__ void transpose_split_qkv_kernel(const float* __restrict__ wq,
                                           const float* __restrict__ wk,
                                           const float* __restrict__ wv,
                                           __nv_bfloat16* __restrict__ oh,
                                           __nv_bfloat16* __restrict__ ol) {
    __shared__ float t[32][33];
    const int z = blockIdx.z;
    const int layer = z & 7;
    const int which = z >> 3;
    const float* in = (which == 0 ? wq : which == 1 ? wk : wv) + (size_t)layer * C_ * C_;
    const size_t obase = (size_t)layer * QKV_ * C_ + (size_t)which * C_ * C_;
    const int k0 = blockIdx.y * 32;
    const int n0 = blockIdx.x * 32;
    #pragma unroll
    for (int j = 0; j < 4; j++) {
        int k = k0 + threadIdx.y + j * 8;
        t[threadIdx.y + j * 8][threadIdx.x] = in[(size_t)k * C_ + n0 + threadIdx.x];
    }
    __syncthreads();
    #pragma unroll
    for (int j = 0; j < 4; j++) {
        int n = n0 + threadIdx.y + j * 8;
        float v = t[threadIdx.x][threadIdx.y + j * 8];
        __nv_bfloat16 h, l;
        split1(v, h, l);
        size_t off = obase + (size_t)n * C_ + k0 + threadIdx.x;
        oh[off] = h;
        ol[off] = l;
    }
}

__global__ void transpose_split_wo_w2_kernel(const float* __restrict__ wo,
                                             const float* __restrict__ w2,
                                             __nv_bfloat16* __restrict__ ooh,
                                             __nv_bfloat16* __restrict__ ool,
                                             __nv_bfloat16* __restrict__ o2h,
                                             __nv_bfloat16* __restrict__ o2l) {
    __shared__ float t[32][33];
    const int layer = blockIdx.z;
    const bool isW2 = (blockIdx.y >= 32);
    const float* in;
    __nv_bfloat16 *oh, *ol;
    int K, k0;
    size_t obase;
    if (!isW2) {
        in = wo + (size_t)layer * C_ * C_; K = C_; k0 = blockIdx.y * 32;
        oh = ooh; ol = ool; obase = (size_t)layer * C_ * C_;
    } else {
        in = w2 + (size_t)layer * F_ * C_; K = F_; k0 = (blockIdx.y - 32) * 32;
        oh = o2h; ol = o2l; obase = (size_t)layer * F_ * C_;
    }
    const int n0 = blockIdx.x * 32;
    #pragma unroll
    for (int j = 0; j < 4; j++) {
        int k = k0 + threadIdx.y + j * 8;
        t[threadIdx.y + j * 8][threadIdx.x] = in[(size_t)k * C_ + n0 + threadIdx.x];
    }
    __syncthreads();
    #pragma unroll
    for (int j = 0; j < 4; j++) {
        int n = n0 + threadIdx.y + j * 8;
        float v = t[threadIdx.x][threadIdx.y + j * 8];
        __nv_bfloat16 h, l;
        split1(v, h, l);
        size_t off = obase + (size_t)n * K + k0 + threadIdx.x;
        oh[off] = h;
        ol[off] = l;
    }
}

// ===========================================================================
// LayerNorm
// ===========================================================================
__global__ void layernorm_bf16_kernel(const float* __restrict__ x,
                                      const float* __restrict__ g,
                                      const float* __restrict__ b,
                                      __nv_bfloat16* __restrict__ yh,
                                      __nv_bfloat16* __restrict__ yl) {
    int row = blockIdx.x;
    int tid = threadIdx.x;
    int c = tid * 4;

    float4 xv = *(const float4*)(x + (size_t)row * C_ + c);
    float s  = xv.x + xv.y + xv.z + xv.w;
    float sq = xv.x*xv.x + xv.y*xv.y + xv.z*xv.z + xv.w*xv.w;

    __shared__ float ssum[256];
    __shared__ float ssq[256];
    ssum[tid] = s; ssq[tid] = sq;
    __syncthreads();
    #pragma unroll
    for (int st = 128; st > 0; st >>= 1) {
        if (tid < st) { ssum[tid] += ssum[tid+st]; ssq[tid] += ssq[tid+st]; }
        __syncthreads();
    }
    __shared__ float s_mean, s_rstd;
    if (tid == 0) {
        float mean = ssum[0] * (1.0f / C_);
        float var  = ssq[0] * (1.0f / C_) - mean * mean;
        s_mean = mean;
        s_rstd = rsqrtf(var + 1e-5f);
    }
    __syncthreads();
    float mean = s_mean, rstd = s_rstd;

    float4 gv = *(const float4*)(g + c);
    float4 bv = *(const float4*)(b + c);
    float4 o;
    o.x = (xv.x - mean) * rstd * gv.x + bv.x;
    o.y = (xv.y - mean) * rstd * gv.y + bv.y;
    o.z = (xv.z - mean) * rstd * gv.z + bv.z;
    o.w = (xv.w - mean) * rstd * gv.w + bv.w;
    split4_store(o, yh + (size_t)row * C_ + c, yl + (size_t)row * C_ + c);
}

__global__ void layernorm_last_kernel(const float* __restrict__ x,
                                      const float* __restrict__ g,
                                      const float* __restrict__ b,
                                      float* __restrict__ y) {
    int row_in  = blockIdx.x * T_ + (T_ - 1);
    int tid = threadIdx.x;
    int c = tid * 4;

    float4 xv = *(const float4*)(x + (size_t)row_in * C_ + c);
    float s  = xv.x + xv.y + xv.z + xv.w;
    float sq = xv.x*xv.x + xv.y*xv.y + xv.z*xv.z + xv.w*xv.w;

    __shared__ float ssum[256];
    __shared__ float ssq[256];
    ssum[tid] = s; ssq[tid] = sq;
    __syncthreads();
    #pragma unroll
    for (int st = 128; st > 0; st >>= 1) {
        if (tid < st) { ssum[tid] += ssum[tid+st]; ssq[tid] += ssq[tid+st]; }
        __syncthreads();
    }
    __shared__ float s_mean, s_rstd;
    if (tid == 0) {
        float mean = ssum[0] * (1.0f / C_);
        float var  = ssq[0] * (1.0f / C_) - mean * mean;
        s_mean = mean;
        s_rstd = rsqrtf(var + 1e-5f);
    }
    __syncthreads();
    float mean = s_mean, rstd = s_rstd;

    float4 gv = *(const float4*)(g + c);
    float4 bv = *(const float4*)(b + c);
    float4 o;
    o.x = (xv.x - mean) * rstd * gv.x + bv.x;
    o.y = (xv.y - mean) * rstd * gv.y + bv.y;
    o.z = (xv.z - mean) * rstd * gv.z + bv.z;
    o.w = (xv.w - mean) * rstd * gv.w + bv.w;
    *(float4*)(y + (size_t)blockIdx.x * C_ + c) = o;
}

// ===========================================================================
// mma.sync split-bf16 GEMM (R8: 256 threads, BM template, MI=BM/32).
// VFUSE: columns n >= 2048 written transposed+split into vth/vtl.
// ===========================================================================
#define SWZ(row, chunk) ((((chunk) ^ ((row) & 7)) << 4) + (row) * 128)
#define GEMM_SMEM 196608

template<int ROWS>
__device__ __forceinline__ void load_tile_cp(const __nv_bfloat16* __restrict__ src,
                                             int row0, int K, int kt,
                                             uint32_t sbase, int tid) {
    #pragma unroll
    for (int r = 0; r < ROWS / 32; r++) {
        int cid = tid + r * 256;
        int row = cid >> 3;
        int c   = cid & 7;
        const __nv_bfloat16* g = src + (size_t)(row0 + row) * K + kt * 64 + c * 8;
        CP_ASYNC16(sbase + SWZ(row, c), g);
    }
}

template<int BM, bool RELU, bool RES, bool OUTBF16, bool VFUSE>
__global__ __launch_bounds__(256, 1)
void gemm_tc(const __nv_bfloat16* __restrict__ Ah, const __nv_bfloat16* __restrict__ Al,
             const __nv_bfloat16* __restrict__ Bh, const __nv_bfloat16* __restrict__ Bl,
             const float* __restrict__ bias, const float* __restrict__ res,
             float* __restrict__ Cf,
             __nv_bfloat16* __restrict__ Ch, __nv_bfloat16* __restrict__ Cl,
             __nv_bfloat16* __restrict__ vth, __nv_bfloat16* __restrict__ vtl,
             int M, int N, int K) {
    constexpr int MI      = BM / 32;
    constexpr int A_TILE  = BM * 128;
    constexpr int B_TILE  = 16384;
    constexpr int STG     = (BM == 128) ? 3 : 2;
    constexpr int STAGE   = 2 * A_TILE + 2 * B_TILE;

    extern __shared__ char dsm[];
    const uint32_t base = smem_u32(dsm);

    const int tid  = threadIdx.x;
    const int wid  = tid >> 5;
    const int lane = tid & 31;
    const int m0 = blockIdx.y * BM;
    const int n0 = blockIdx.x * 128;
    const int wm = wid & 1;
    const int wn = wid >> 1;

    float acc[MI][4][4];
    #pragma unroll
    for (int i = 0; i < MI; i++)
        #pragma unroll
        for (int j = 0; j < 4; j++)
            #pragma unroll
            for (int r = 0; r < 4; r++) acc[i][j][r] = 0.0f;

    const int nkt = K >> 6;

    const int a_row  = wm * (BM / 2) + (lane & 15);
    const int a_csel = lane >> 4;
    const int b_row  = wn * 32 + ((lane & 7) | ((lane & 16) >> 1));
    const int b_csel = (lane >> 3) & 1;

    {
        load_tile_cp<BM>(Ah, m0, K, 0, base, tid);
        load_tile_cp<BM>(Al, m0, K, 0, base + A_TILE, tid);
        load_tile_cp<128>(Bh, n0, K, 0, base + 2 * A_TILE, tid);
        load_tile_cp<128>(Bl, n0, K, 0, base + 2 * A_TILE + B_TILE, tid);
        CP_COMMIT();
        load_tile_cp<BM>(Ah, m0, K, 1, base + STAGE, tid);
        load_tile_cp<BM>(Al, m0, K, 1, base + STAGE + A_TILE, tid);
        load_tile_cp<128>(Bh, n0, K, 1, base + STAGE + 2 * A_TILE, tid);
        load_tile_cp<128>(Bl, n0, K, 1, base + STAGE + 2 * A_TILE + B_TILE, tid);
        CP_COMMIT();
    }

    for (int kt = 0; kt < nkt; kt++) {
        if (kt + 1 < nkt) { CP_WAIT1(); } else { CP_WAIT0(); }
        __syncthreads();

        if (STG == 3 && kt + 2 < nkt) {
            const uint32_t nb = base + ((kt + 2) % 3) * STAGE;
            load_tile_cp<BM>(Ah, m0, K, kt + 2, nb, tid);
            load_tile_cp<BM>(Al, m0, K, kt + 2, nb + A_TILE, tid);
            load_tile_cp<128>(Bh, n0, K, kt + 2, nb + 2 * A_TILE, tid);
            load_tile_cp<128>(Bl, n0, K, kt + 2, nb + 2 * A_TILE + B_TILE, tid);
            CP_COMMIT();
        }

        const uint32_t sb  = base + (kt % STG) * STAGE;
        const uint32_t sAh = sb;
        const uint32_t sAl = sb + A_TILE;
        const uint32_t sBh = sb + 2 * A_TILE;
        const uint32_t sBl = sb + 2 * A_TILE + B_TILE;

        #pragma unroll
        for (int ks = 0; ks < 4; ks++) {
            const int ac = ks * 2 + a_csel;
            const int bc = ks * 2 + b_csel;
            uint32_t bh[4][2], bl[4][2];
            #pragma unroll
            for (int nj = 0; nj < 2; nj++) {
                int row = b_row + nj * 16;
                ldm_x4(sBh + SWZ(row, bc), bh[nj*2][0], bh[nj*2][1], bh[nj*2+1][0], bh[nj*2+1][1]);
                ldm_x4(sBl + SWZ(row, bc), bl[nj*2][0], bl[nj*2][1], bl[nj*2+1][0], bl[nj*2+1][1]);
            }
            #pragma unroll
            for (int mi = 0; mi < MI; mi++) {
                uint32_t ah0, ah1, ah2, ah3, al0, al1, al2, al3;
                int row = a_row + mi * 16;
                ldm_x4(sAh + SWZ(row, ac), ah0, ah1, ah2, ah3);
                ldm_x4(sAl + SWZ(row, ac), al0, al1, al2, al3);
                #pragma unroll
                for (int ni = 0; ni < 4; ni++) {
                    mma_bf16(acc[mi][ni][0], acc[mi][ni][1], acc[mi][ni][2], acc[mi][ni][3],
                             ah0, ah1, ah2, ah3, bh[ni][0], bh[ni][1]);
                    mma_bf16(acc[mi][ni][0], acc[mi][ni][1], acc[mi][ni][2], acc[mi][ni][3],
                             ah0, ah1, ah2, ah3, bl[ni][0], bl[ni][1]);
                    mma_bf16(acc[mi][ni][0], acc[mi][ni][1], acc[mi][ni][2], acc[mi][ni][3],
                             al0, al1, al2, al3, bh[ni][0], bh[ni][1]);
                }
            }
        }

        if (STG == 2) {
            __syncthreads();
            if (kt + 2 < nkt) {
                const uint32_t nb = base + (kt & 1) * STAGE;
                load_tile_cp<BM>(Ah, m0, K, kt + 2, nb, tid);
                load_tile_cp<BM>(Al, m0, K, kt + 2, nb + A_TILE, tid);
                load_tile_cp<128>(Bh, n0, K, kt + 2, nb + 2 * A_TILE, tid);
                load_tile_cp<128>(Bl, n0, K, kt + 2, nb + 2 * A_TILE + B_TILE, tid);
                CP_COMMIT();
            }
        }
    }

    const int qm = lane >> 2;
    const int qn = (lane & 3) * 2;
    const bool vblock = VFUSE && (n0 >= 2 * C_);
    #pragma unroll
    for (int mi = 0; mi < MI; mi++) {
        #pragma unroll
        for (int ni = 0; ni < 4; ni++) {
            const int n = n0 + wn * 32 + ni * 8 + qn;
            float2 bv = *(const float2*)(bias + n);
            #pragma unroll
            for (int half = 0; half < 2; half++) {
                const int m = m0 + wm * (BM / 2) + mi * 16 + qm + half * 8;
                float vx = acc[mi][ni][half*2 + 0] + bv.x;
                float vy = acc[mi][ni][half*2 + 1] + bv.y;
                if (RELU) { vx = fmaxf(vx, 0.f); vy = fmaxf(vy, 0.f); }
                if (RES) {
                    float2 rv = *(const float2*)(res + (size_t)m * N + n);
                    vx += rv.x; vy += rv.y;
                }
                if (vblock) {
                    const int t  = m & (T_ - 1);
                    const int bb = m >> 11;
                    const int nv = n - 2 * C_;
                    const int hh = nv >> 6;
                    const int d  = nv & 63;
                    __nv_bfloat16 h0, l0, h1, l1;
                    split1(vx, h0, l0);
                    split1(vy, h1, l1);
                    size_t vo = ((size_t)(bb * H_ + hh) * 64 + d) * T_ + t;
                    vth[vo]      = h0;
                    vth[vo + T_] = h1;
                    vtl[vo]      = l0;
                    vtl[vo + T_] = l1;
                } else if (OUTBF16) {
                    split2_store(vx, vy, Ch + (size_t)m * N + n, Cl + (size_t)m * N + n);
                } else {
                    *(float2*)(Cf + (size_t)m * N + n) = make_float2(vx, vy);
                }
            }
        }
    }
}

// ===========================================================================
// Tensor-core flash attention (R8: 64 queries/CTA, 4 warps)
// ===========================================================================
#define ATT_SMEM (16384 + 32768)

__global__ __launch_bounds__(128)
void attention_mma_kernel(const __nv_bfloat16* __restrict__ qkvh,
                          const __nv_bfloat16* __restrict__ qkvl,
                          const __nv_bfloat16* __restrict__ Vth,
                          const __nv_bfloat16* __restrict__ Vtl,
                          __nv_bfloat16* __restrict__ aoh,
                          __nv_bfloat16* __restrict__ aol) {
    extern __shared__ char dsm[];
    const uint32_t base = smem_u32(dsm);
    const uint32_t sQh = base;
    const uint32_t sQl = base + 8192;
    const uint32_t sKh = base + 16384;
    const uint32_t sKl = base + 24576;
    const uint32_t sVh = base + 32768;
    const uint32_t sVl = base + 40960;

    const int b  = blockIdx.z;
    const int h  = blockIdx.y;
    const int qt = (T_ / 64 - 1) - blockIdx.x;
    const int tid  = threadIdx.x;
    const int wid  = tid >> 5;
    const int lane = tid & 31;
    const int m_base = wid * 16;

    #pragma unroll
    for (int r = 0; r < 4; r++) {
        int cid = tid + r * 128;
        int row = cid >> 3;
        int c   = cid & 7;
        size_t goff = (size_t)(b * T_ + qt * 64 + row) * QKV_ + h * 64 + c * 8;
        CP_ASYNC16(sQh + SWZ(row, c), qkvh + goff);
        CP_ASYNC16(sQl + SWZ(row, c), qkvl + goff);
    }
    CP_COMMIT(); CP_WAIT0();
    __syncthreads();

    const int a_row  = m_base + (lane & 15);
    const int a_csel = lane >> 4;
    uint32_t qfh[4][4], qfl[4][4];
    #pragma unroll
    for (int ks = 0; ks < 4; ks++) {
        ldm_x4(sQh + SWZ(a_row, ks*2 + a_csel), qfh[ks][0], qfh[ks][1], qfh[ks][2], qfh[ks][3]);
        ldm_x4(sQl + SWZ(a_row, ks*2 + a_csel), qfl[ks][0], qfl[ks][1], qfl[ks][2], qfl[ks][3]);
    }

    const int b_row_l = (lane & 7) | ((lane & 16) >> 1);
    const int b_csel  = (lane >> 3) & 1;
    const int qm = lane >> 2;
    const int qn = (lane & 3) * 2;

    float o[8][4];
    #pragma unroll
    for (int n = 0; n < 8; n++)
        #pragma unroll
        for (int r = 0; r < 4; r++) o[n][r] = 0.0f;
    float mrow[2] = {-FLT_MAX, -FLT_MAX};
    float lrow[2] = {0.0f, 0.0f};

    for (int kt = 0; kt <= qt; kt++) {
        __syncthreads();
        #pragma unroll
        for (int r = 0; r < 4; r++) {
            int cid = tid + r * 128;
            int row = cid >> 3;
            int c   = cid & 7;
            size_t koff = (size_t)(b * T_ + kt * 64 + row) * QKV_ + C_ + h * 64 + c * 8;
            size_t voff = ((size_t)(b * H_ + h) * 64 + row) * T_ + kt * 64 + c * 8;
            CP_ASYNC16(sKh + SWZ(row, c), qkvh + koff);
            CP_ASYNC16(sKl + SWZ(row, c), qkvl + koff);
            CP_ASYNC16(sVh + SWZ(row, c), Vth + voff);
            CP_ASYNC16(sVl + SWZ(row, c), Vtl + voff);
        }
        CP_COMMIT(); CP_WAIT0();
        __syncthreads();

        float sc[8][4];
        #pragma unroll
        for (int n = 0; n < 8; n++)
            #pragma unroll
            for (int r = 0; r < 4; r++) sc[n][r] = 0.0f;

        #pragma unroll
        for (int ks = 0; ks < 4; ks++) {
            const int bc = ks * 2 + b_csel;
            #pragma unroll
            for (int g = 0; g < 4; g++) {
                uint32_t r0, r1, r2, r3, s0, s1, s2, s3;
                ldm_x4(sKh + SWZ(g * 16 + b_row_l, bc), r0, r1, r2, r3);
                ldm_x4(sKl + SWZ(g * 16 + b_row_l, bc), s0, s1, s2, s3);
                mma_bf16(sc[2*g][0], sc[2*g][1], sc[2*g][2], sc[2*g][3],
                         qfh[ks][0], qfh[ks][1], qfh[ks][2], qfh[ks][3], r0, r1);
                mma_bf16(sc[2*g+1][0], sc[2*g+1][1], sc[2*g+1][2], sc[2*g+1][3],
                         qfh[ks][0], qfh[ks][1], qfh[ks][2], qfh[ks][3], r2, r3);
                mma_bf16(sc[2*g][0], sc[2*g][1], sc[2*g][2], sc[2*g][3],
                         qfh[ks][0], qfh[ks][1], qfh[ks][2], qfh[ks][3], s0, s1);
                mma_bf16(sc[2*g+1][0], sc[2*g+1][1], sc[2*g+1][2], sc[2*g+1][3],
                         qfh[ks][0], qfh[ks][1], qfh[ks][2], qfh[ks][3], s2, s3);
                mma_bf16(sc[2*g][0], sc[2*g][1], sc[2*g][2], sc[2*g][3],
                         qfl[ks][0], qfl[ks][1], qfl[ks][2], qfl[ks][3], r0, r1);
                mma_bf16(sc[2*g+1][0], sc[2*g+1][1], sc[2*g+1][2], sc[2*g+1][3],
                         qfl[ks][0], qfl[ks][1], qfl[ks][2], qfl[ks][3], r2, r3);
            }
        }

        #pragma unroll
        for (int n = 0; n < 8; n++)
            #pragma unroll
            for (int r = 0; r < 4; r++) sc[n][r] *= 0.125f;

        if (kt == qt) {
            const int row0 = m_base + qm;
            const int row1 = row0 + 8;
            #pragma unroll
            for (int n = 0; n < 8; n++) {
                int col = n * 8 + qn;
                if (col     > row0) sc[n][0] = -FLT_MAX;
                if (col + 1 > row0) sc[n][1] = -FLT_MAX;
                if (col     > row1) sc[n][2] = -FLT_MAX;
                if (col + 1 > row1) sc[n][3] = -FLT_MAX;
            }
        }

        #pragma unroll
        for (int r = 0; r < 2; r++) {
            float mx = -FLT_MAX;
            #pragma unroll
            for (int n = 0; n < 8; n++) {
                mx = fmaxf(mx, sc[n][2*r]);
                mx = fmaxf(mx, sc[n][2*r + 1]);
            }
            mx = fmaxf(mx, __shfl_xor_sync(0xffffffffu, mx, 1));
            mx = fmaxf(mx, __shfl_xor_sync(0xffffffffu, mx, 2));
            float mnew = fmaxf(mrow[r], mx);
            float alpha = __expf(mrow[r] - mnew);
            float sum = 0.0f;
            #pragma unroll
            for (int n = 0; n < 8; n++) {
                float p0 = __expf(sc[n][2*r]     - mnew);
                float p1 = __expf(sc[n][2*r + 1] - mnew);
                sc[n][2*r]     = p0;
                sc[n][2*r + 1] = p1;
                sum += p0 + p1;
            }
            sum += __shfl_xor_sync(0xffffffffu, sum, 1);
            sum += __shfl_xor_sync(0xffffffffu, sum, 2);
            lrow[r] = lrow[r] * alpha + sum;
            mrow[r] = mnew;
            #pragma unroll
            for (int n = 0; n < 8; n++) {
                o[n][2*r]     *= alpha;
                o[n][2*r + 1] *= alpha;
            }
        }

        #pragma unroll
        for (int ks = 0; ks < 4; ks++) {
            uint32_t ph0, ph1, ph2, ph3, pl0, pl1, pl2, pl3;
            pack_split(sc[2*ks][0],   sc[2*ks][1],   ph0, pl0);
            pack_split(sc[2*ks][2],   sc[2*ks][3],   ph1, pl1);
            pack_split(sc[2*ks+1][0], sc[2*ks+1][1], ph2, pl2);
            pack_split(sc[2*ks+1][2], sc[2*ks+1][3], ph3, pl3);
            const int bc = ks * 2 + b_csel;
            #pragma unroll
            for (int g = 0; g < 4; g++) {
                uint32_t r0, r1, r2, r3, s0, s1, s2, s3;
                ldm_x4(sVh + SWZ(g * 16 + b_row_l, bc), r0, r1, r2, r3);
                ldm_x4(sVl + SWZ(g * 16 + b_row_l, bc), s0, s1, s2, s3);
                mma_bf16(o[2*g][0], o[2*g][1], o[2*g][2], o[2*g][3],
                         ph0, ph1, ph2, ph3, r0, r1);
                mma_bf16(o[2*g+1][0], o[2*g+1][1], o[2*g+1][2], o[2*g+1][3],
                         ph0, ph1, ph2, ph3, r2, r3);
                mma_bf16(o[2*g][0], o[2*g][1], o[2*g][2], o[2*g][3],
                         ph0, ph1, ph2, ph3, s0, s1);
                mma_bf16(o[2*g+1][0], o[2*g+1][1], o[2*g+1][2], o[2*g+1][3],
                         ph0, ph1, ph2, ph3, s2, s3);
                mma_bf16(o[2*g][0], o[2*g][1], o[2*g][2], o[2*g][3],
                         pl0, pl1, pl2, pl3, r0, r1);
                mma_bf16(o[2*g+1][0], o[2*g+1][1], o[2*g+1][2], o[2*g+1][3],
                         pl0, pl1, pl2, pl3, r2, r3);
            }
        }
    }

    const float inv0 = 1.0f / lrow[0];
    const float inv1 = 1.0f / lrow[1];
    const size_t row0 = (size_t)(b * T_ + qt * 64 + m_base + qm) * C_;
    const size_t row1 = row0 + 8 * C_;
    #pragma unroll
    for (int n = 0; n < 8; n++) {
        int col = h * 64 + n * 8 + qn;
        split2_store(o[n][0] * inv0, o[n][1] * inv0, aoh + row0 + col, aol + row0 + col);
        split2_store(o[n][2] * inv1, o[n][3] * inv1, aoh + row1 + col, aol + row1 + col);
    }
}

// ===========================================================================
// Logits — one block serves both batches (W read once)
// ===========================================================================
__global__ void logits_kernel(const float* __restrict__ xf,
                              const float* __restrict__ W,
                              const float* __restrict__ bias,
                              float* __restrict__ out) {
    __shared__ float xs0[C_];
    __shared__ float xs1[C_];
    const int tid = threadIdx.x;
    #pragma unroll
    for (int r = 0; r < C_ / 128; r++) {
        xs0[tid + r * 128] = xf[tid + r * 128];
        xs1[tid + r * 128] = xf[C_ + tid + r * 128];
    }
    __syncthreads();

    int vcol = blockIdx.x * 128 + tid;
    float bb = bias[vcol];
    float acc0 = bb, acc1 = bb;
    const float* wp = W + vcol;
    #pragma unroll 8
    for (int k = 0; k < C_; k++) {
        float w = wp[(size_t)k * V_];
        acc0 = fmaf(xs0[k], w, acc0);
        acc1 = fmaf(xs1[k], w, acc1);
    }
    out[vcol]      = acc0;
    out[V_ + vcol] = acc1;
}

// ===========================================================================
// Launch (R12 structure; MLP1 moved to BM=256)
// ===========================================================================
extern "C" void kernel_launch(void* const* d_in, const int* in_sizes, int n_in,
                              void* d_out, int out_size) {
    const int*   idx   = (const int*)  d_in[0];
    const float* emb   = (const float*)d_in[1];
    const float* pos   = (const float*)d_in[2];
    const float* ln1_g = (const float*)d_in[3];
    const float* ln1_b = (const float*)d_in[4];
    const float* wq    = (const float*)d_in[5];
    const float* bq    = (const float*)d_in[6];
    const float* wk    = (const float*)d_in[7];
    const float* bk    = (const float*)d_in[8];
    const float* wv    = (const float*)d_in[9];
    const float* bv    = (const float*)d_in[10];
    const float* wo    = (const float*)d_in[11];
    const float* bo    = (const float*)d_in[12];
    const float* ln2_g = (const float*)d_in[13];
    const float* ln2_b = (const float*)d_in[14];
    const float* w1    = (const float*)d_in[15];
    const float* b1    = (const float*)d_in[16];
    const float* w2    = (const float*)d_in[17];
    const float* b2    = (const float*)d_in[18];
    const float* lnf_g = (const float*)d_in[19];
    const float* lnf_b = (const float*)d_in[20];
    const float* out_w = (const float*)d_in[21];
    const float* out_b = (const float*)d_in[22];
    float* out = (float*)d_out;

    float *x, *xf, *bqkv;
    cudaGetSymbolAddress((void**)&x,    g_x);
    cudaGetSymbolAddress((void**)&xf,   g_xf);
    cudaGetSymbolAddress((void**)&bqkv, g_bqkv);

    __nv_bfloat16 *h_h, *h_l, *qkvh, *qkvl, *vth, *vtl, *ao_h, *ao_l, *hid_h, *hid_l;
    cudaGetSymbolAddress((void**)&h_h,   g_h_h);
    cudaGetSymbolAddress((void**)&h_l,   g_h_l);
    cudaGetSymbolAddress((void**)&qkvh,  g_qkvh);
    cudaGetSymbolAddress((void**)&qkvl,  g_qkvl);
    cudaGetSymbolAddress((void**)&vth,   g_vth);
    cudaGetSymbolAddress((void**)&vtl,   g_vtl);
    cudaGetSymbolAddress((void**)&ao_h,  g_ao_h);
    cudaGetSymbolAddress((void**)&ao_l,  g_ao_l);
    cudaGetSymbolAddress((void**)&hid_h, g_hid_h);
    cudaGetSymbolAddress((void**)&hid_l, g_hid_l);

    __nv_bfloat16 *wqkvT_h, *wqkvT_l, *woT_h, *woT_l, *w1T_h, *w1T_l, *w2T_h, *w2T_l;
    cudaGetSymbolAddress((void**)&wqkvT_h, g_wqkvT_h);
    cudaGetSymbolAddress((void**)&wqkvT_l, g_wqkvT_l);
    cudaGetSymbolAddress((void**)&woT_h, g_woT_h);
    cudaGetSymbolAddress((void**)&woT_l, g_woT_l);
    cudaGetSymbolAddress((void**)&w1T_h, g_w1T_h);
    cudaGetSymbolAddress((void**)&w1T_l, g_w1T_l);
    cudaGetSymbolAddress((void**)&w2T_h, g_w2T_h);
    cudaGetSymbolAddress((void**)&w2T_l, g_w2T_l);

    cudaFuncSetAttribute(gemm_tc<256, false, false, true, true>,
                         cudaFuncAttributeMaxDynamicSharedMemorySize, GEMM_SMEM);
    cudaFuncSetAttribute(gemm_tc<256, true, false, true, false>,
                         cudaFuncAttributeMaxDynamicSharedMemorySize, GEMM_SMEM);
    cudaFuncSetAttribute(gemm_tc<256, false, true, false, false>,
                         cudaFuncAttributeMaxDynamicSharedMemorySize, GEMM_SMEM);
    cudaFuncSetAttribute(attention_mma_kernel,
                         cudaFuncAttributeMaxDynamicSharedMemorySize, ATT_SMEM);

    // Weight prep: 3 launches (R8 config)
    {
        dim3 blk(32, 8);
        transpose_split_qkv_kernel<<<dim3(32, 32, 24), blk>>>(wq, wk, wv, wqkvT_h, wqkvT_l);
        transpose_split_wo_w2_kernel<<<dim3(32, 160, 8), blk>>>(wo, w2, woT_h, woT_l, w2T_h, w2T_l);
        transpose_split_kernel<<<dim3(128, 32, 8), blk>>>(w1, w1T_h, w1T_l, C_, F_, (size_t)C_ * F_);
    }

    embed_kernel<<<BT_, 256>>>(idx, emb, pos, bq, bk, bv, x, bqkv);

    dim3 gemm_qkv(QKV_ / 128, BT_ / 256);  // (24, 16)  BM=256, V fused-transposed
    dim3 gemm_cc(C_ / 128, BT_ / 256);     // (8, 16)   BM=256
    dim3 gemm_cf(F_ / 128, BT_ / 256);     // (32, 16)  BM=256  (MLP1, was BM=128)
    dim3 attn_grid(T_ / 64, H_, B_);

    for (int l = 0; l < L_; l++) {
        layernorm_bf16_kernel<<<BT_, 256>>>(x, ln1_g + l * C_, ln1_b + l * C_, h_h, h_l);

        // merged QKV projection; V columns written straight into vt layout
        gemm_tc<256, false, false, true, true><<<gemm_qkv, 256, GEMM_SMEM>>>(
            h_h, h_l, wqkvT_h + (size_t)l * QKV_ * C_, wqkvT_l + (size_t)l * QKV_ * C_,
            bqkv + l * QKV_, nullptr, nullptr, qkvh, qkvl, vth, vtl, BT_, QKV_, C_);

        attention_mma_kernel<<<attn_grid, 128, ATT_SMEM>>>(
            qkvh, qkvl, vth, vtl, ao_h, ao_l);

        // x = x + (ao @ wo + bo)
        gemm_tc<256, false, true, false, false><<<gemm_cc, 256, GEMM_SMEM>>>(
            ao_h, ao_l, woT_h + (size_t)l * C_ * C_, woT_l + (size_t)l * C_ * C_,
            bo + l * C_, x, x, nullptr, nullptr, nullptr, nullptr, BT_, C_, C_);

        layernorm_bf16_kernel<<<BT_, 256>>>(x, ln2_g + l * C_, ln2_b + l * C_, h_h, h_l);

        // hid = relu(h @ w1 + b1)   (BM=256 now)
        gemm_tc<256, true, false, true, false><<<gemm_cf, 256, GEMM_SMEM>>>(
            h_h, h_l, w1T_h + (size_t)l * C_ * F_, w1T_l + (size_t)l * C_ * F_,
            b1 + l * F_, nullptr, nullptr, hid_h, hid_l, nullptr, nullptr, BT_, F_, C_);
        // x = x + (hid @ w2 + b2)
        gemm_tc<256, false, true, false, false><<<gemm_cc, 256, GEMM_SMEM>>>(
            hid_h, hid_l, w2T_h + (size_t)l * F_ * C_, w2T_l + (size_t)l * F_ * C_,
            b2 + l * C_, x, x, nullptr, nullptr, nullptr, nullptr, BT_, C_, F_);
    }

    layernorm_last_kernel<<<B_, 256>>>(x, lnf_g, lnf_b, xf);
    logits_kernel<<<V_ / 128, 128>>>(xf, out_w, out_b, out);
}

// round 15
// speedup vs baseline: 1.0269x; 1.0269x over previous
#include <cuda_runtime.h>
#include <cuda_bf16.h>
#include <float.h>
#include <cstdint>

// Problem constants
#define V_   32000
#define C_   1024
#define H_   16
#define L_   8
#define F_   4096
#define B_   2
#define T_   2048
#define D_   64
#define BT_  (B_*T_)
#define QKV_ (3*C_)

// ===========================================================================
// helpers
// ===========================================================================
__device__ __forceinline__ uint32_t smem_u32(const void* p) {
    uint32_t a;
    asm("{ .reg .u64 t; cvta.to.shared.u64 t, %1; cvt.u32.u64 %0, t; }"
        : "=r"(a) : "l"(p));
    return a;
}

#define CP_ASYNC16(saddr, gptr) \
    asm volatile("cp.async.cg.shared.global [%0], [%1], 16;" \
                 :: "r"(saddr), "l"(gptr) : "memory")
#define CP_COMMIT() asm volatile("cp.async.commit_group;" ::: "memory")
#define CP_WAIT1()  asm volatile("cp.async.wait_group 1;" ::: "memory")
#define CP_WAIT0()  asm volatile("cp.async.wait_group 0;" ::: "memory")

__device__ __forceinline__ void ldm_x4(uint32_t addr, uint32_t& r0, uint32_t& r1,
                                       uint32_t& r2, uint32_t& r3) {
    asm volatile("ldmatrix.sync.aligned.m8n8.x4.shared.b16 {%0,%1,%2,%3}, [%4];"
                 : "=r"(r0), "=r"(r1), "=r"(r2), "=r"(r3) : "r"(addr));
}

__device__ __forceinline__ void mma_bf16(float& d0, float& d1, float& d2, float& d3,
                                         uint32_t a0, uint32_t a1, uint32_t a2, uint32_t a3,
                                         uint32_t b0, uint32_t b1) {
    asm volatile(
        "mma.sync.aligned.m16n8k16.row.col.f32.bf16.bf16.f32 "
        "{%0,%1,%2,%3}, {%4,%5,%6,%7}, {%8,%9}, {%0,%1,%2,%3};"
        : "+f"(d0), "+f"(d1), "+f"(d2), "+f"(d3)
        : "r"(a0), "r"(a1), "r"(a2), "r"(a3), "r"(b0), "r"(b1));
}

// bf16 hi/lo split helpers
__device__ __forceinline__ void split1(float v, __nv_bfloat16& h, __nv_bfloat16& l) {
    h = __float2bfloat16(v);
    l = __float2bfloat16(v - __bfloat162float(h));
}
__device__ __forceinline__ void split2_store(float x, float y,
                                             __nv_bfloat16* ph, __nv_bfloat16* pl) {
    __nv_bfloat16 h0, h1, l0, l1;
    split1(x, h0, l0); split1(y, h1, l1);
    __nv_bfloat162 H; H.x = h0; H.y = h1;
    __nv_bfloat162 L; L.x = l0; L.y = l1;
    *(__nv_bfloat162*)ph = H;
    *(__nv_bfloat162*)pl = L;
}
__device__ __forceinline__ void split4_store(float4 v, __nv_bfloat16* ph, __nv_bfloat16* pl) {
    split2_store(v.x, v.y, ph, pl);
    split2_store(v.z, v.w, ph + 2, pl + 2);
}
__device__ __forceinline__ void pack_split(float x, float y, uint32_t& hi, uint32_t& lo) {
    __nv_bfloat16 hx, lx, hy, ly;
    split1(x, hx, lx); split1(y, hy, ly);
    __nv_bfloat162 Hh; Hh.x = hx; Hh.y = hy;
    __nv_bfloat162 Ll; Ll.x = lx; Ll.y = ly;
    hi = *reinterpret_cast<uint32_t*>(&Hh);
    lo = *reinterpret_cast<uint32_t*>(&Ll);
}

// ===========================================================================
// Scratch
// ===========================================================================
__device__ float g_x  [BT_ * C_];
__device__ float g_xf [B_ * C_];
__device__ float g_bqkv[L_ * QKV_];

__device__ __nv_bfloat16 g_h_h  [BT_ * C_];
__device__ __nv_bfloat16 g_h_l  [BT_ * C_];
__device__ __nv_bfloat16 g_qkvh [(size_t)BT_ * QKV_];
__device__ __nv_bfloat16 g_qkvl [(size_t)BT_ * QKV_];
__device__ __nv_bfloat16 g_vth  [B_ * H_ * D_ * T_];
__device__ __nv_bfloat16 g_vtl  [B_ * H_ * D_ * T_];
__device__ __nv_bfloat16 g_ao_h [BT_ * C_];
__device__ __nv_bfloat16 g_ao_l [BT_ * C_];
__device__ __nv_bfloat16 g_hid_h[BT_ * F_];
__device__ __nv_bfloat16 g_hid_l[BT_ * F_];

__device__ __nv_bfloat16 g_wqkvT_h[(size_t)L_ * QKV_ * C_];
__device__ __nv_bfloat16 g_wqkvT_l[(size_t)L_ * QKV_ * C_];
__device__ __nv_bfloat16 g_woT_h[L_ * C_ * C_];
__device__ __nv_bfloat16 g_woT_l[L_ * C_ * C_];
__device__ __nv_bfloat16 g_w1T_h[L_ * C_ * F_];
__device__ __nv_bfloat16 g_w1T_l[L_ * C_ * F_];
__device__ __nv_bfloat16 g_w2T_h[L_ * F_ * C_];
__device__ __nv_bfloat16 g_w2T_l[L_ * F_ * C_];

// ===========================================================================
// Embedding (+ QKV bias concat)
// ===========================================================================
__global__ void embed_kernel(const int* __restrict__ idx,
                             const float* __restrict__ emb,
                             const float* __restrict__ pos,
                             const float* __restrict__ bq,
                             const float* __restrict__ bk,
                             const float* __restrict__ bv,
                             float* __restrict__ x,
                             float* __restrict__ bqkv) {
    int row = blockIdx.x;
    int t   = row % T_;
    int tok = idx[row];
    int c   = threadIdx.x * 4;
    float4 e = *(const float4*)(emb + (size_t)tok * C_ + c);
    float4 p = *(const float4*)(pos + (size_t)t   * C_ + c);
    float4 o;
    o.x = e.x + p.x; o.y = e.y + p.y; o.z = e.z + p.z; o.w = e.w + p.w;
    *(float4*)(x + (size_t)row * C_ + c) = o;

    if (blockIdx.x < (L_ * QKV_) / 256) {
        int i = blockIdx.x * 256 + threadIdx.x;
        int layer = i / QKV_;
        int col   = i % QKV_;
        float v;
        if (col < C_)           v = bq[layer * C_ + col];
        else if (col < 2 * C_)  v = bk[layer * C_ + col - C_];
        else                    v = bv[layer * C_ + col - 2 * C_];
        bqkv[i] = v;
    }
}

// ===========================================================================
// Weight transposes + bf16 split — 3 launches.
// ===========================================================================
__global__ void transpose_split_kernel(const float* __restrict__ in,
                                       __nv_bfloat16* __restrict__ oh,
                                       __nv_bfloat16* __restrict__ ol,
                                       int K, int N, size_t out_lstride) {
    __shared__ float t[32][33];
    const float* inl = in + (size_t)blockIdx.z * K * N;
    const size_t obase = (size_t)blockIdx.z * out_lstride;
    const int k0 = blockIdx.y * 32;
    const int n0 = blockIdx.x * 32;
    #pragma unroll
    for (int j = 0; j < 4; j++) {
        int k = k0 + threadIdx.y + j * 8;
        t[threadIdx.y + j * 8][threadIdx.x] = inl[(size_t)k * N + n0 + threadIdx.x];
    }
    __syncthreads();
    #pragma unroll
    for (int j = 0; j < 4; j++) {
        int n = n0 + threadIdx.y + j * 8;
        float v = t[threadIdx.x][threadIdx.y + j * 8];
        __nv_bfloat16 h, l;
        split1(v, h, l);
        size_t off = obase + (size_t)n * K + k0 + threadIdx.x;
        oh[off] = h;
        ol[off] = l;
    }
}

__global__ void transpose_split_qkv_kernel(const float* __restrict__ wq,
                                           const float* __restrict__ wk,
                                           const float* __restrict__ wv,
                                           __nv_bfloat16* __restrict__ oh,
                                           __nv_bfloat16* __restrict__ ol) {
    __shared__ float t[32][33];
    const int z = blockIdx.z;
    const int layer = z & 7;
    const int which = z >> 3;
    const float* in = (which == 0 ? wq : which == 1 ? wk : wv) + (size_t)layer * C_ * C_;
    const size_t obase = (size_t)layer * QKV_ * C_ + (size_t)which * C_ * C_;
    const int k0 = blockIdx.y * 32;
    const int n0 = blockIdx.x * 32;
    #pragma unroll
    for (int j = 0; j < 4; j++) {
        int k = k0 + threadIdx.y + j * 8;
        t[threadIdx.y + j * 8][threadIdx.x] = in[(size_t)k * C_ + n0 + threadIdx.x];
    }
    __syncthreads();
    #pragma unroll
    for (int j = 0; j < 4; j++) {
        int n = n0 + threadIdx.y + j * 8;
        float v = t[threadIdx.x][threadIdx.y + j * 8];
        __nv_bfloat16 h, l;
        split1(v, h, l);
        size_t off = obase + (size_t)n * C_ + k0 + threadIdx.x;
        oh[off] = h;
        ol[off] = l;
    }
}

__global__ void transpose_split_wo_w2_kernel(const float* __restrict__ wo,
                                             const float* __restrict__ w2,
                                             __nv_bfloat16* __restrict__ ooh,
                                             __nv_bfloat16* __restrict__ ool,
                                             __nv_bfloat16* __restrict__ o2h,
                                             __nv_bfloat16* __restrict__ o2l) {
    __shared__ float t[32][33];
    const int layer = blockIdx.z;
    const bool isW2 = (blockIdx.y >= 32);
    const float* in;
    __nv_bfloat16 *oh, *ol;
    int K, k0;
    size_t obase;
    if (!isW2) {
        in = wo + (size_t)layer * C_ * C_; K = C_; k0 = blockIdx.y * 32;
        oh = ooh; ol = ool; obase = (size_t)layer * C_ * C_;
    } else {
        in = w2 + (size_t)layer * F_ * C_; K = F_; k0 = (blockIdx.y - 32) * 32;
        oh = o2h; ol = o2l; obase = (size_t)layer * F_ * C_;
    }
    const int n0 = blockIdx.x * 32;
    #pragma unroll
    for (int j = 0; j < 4; j++) {
        int k = k0 + threadIdx.y + j * 8;
        t[threadIdx.y + j * 8][threadIdx.x] = in[(size_t)k * C_ + n0 + threadIdx.x];
    }
    __syncthreads();
    #pragma unroll
    for (int j = 0; j < 4; j++) {
        int n = n0 + threadIdx.y + j * 8;
        float v = t[threadIdx.x][threadIdx.y + j * 8];
        __nv_bfloat16 h, l;
        split1(v, h, l);
        size_t off = obase + (size_t)n * K + k0 + threadIdx.x;
        oh[off] = h;
        ol[off] = l;
    }
}

// ===========================================================================
// LayerNorm
// ===========================================================================
__global__ void layernorm_bf16_kernel(const float* __restrict__ x,
                                      const float* __restrict__ g,
                                      const float* __restrict__ b,
                                      __nv_bfloat16* __restrict__ yh,
                                      __nv_bfloat16* __restrict__ yl) {
    int row = blockIdx.x;
    int tid = threadIdx.x;
    int c = tid * 4;

    float4 xv = *(const float4*)(x + (size_t)row * C_ + c);
    float s  = xv.x + xv.y + xv.z + xv.w;
    float sq = xv.x*xv.x + xv.y*xv.y + xv.z*xv.z + xv.w*xv.w;

    __shared__ float ssum[256];
    __shared__ float ssq[256];
    ssum[tid] = s; ssq[tid] = sq;
    __syncthreads();
    #pragma unroll
    for (int st = 128; st > 0; st >>= 1) {
        if (tid < st) { ssum[tid] += ssum[tid+st]; ssq[tid] += ssq[tid+st]; }
        __syncthreads();
    }
    __shared__ float s_mean, s_rstd;
    if (tid == 0) {
        float mean = ssum[0] * (1.0f / C_);
        float var  = ssq[0] * (1.0f / C_) - mean * mean;
        s_mean = mean;
        s_rstd = rsqrtf(var + 1e-5f);
    }
    __syncthreads();
    float mean = s_mean, rstd = s_rstd;

    float4 gv = *(const float4*)(g + c);
    float4 bv = *(const float4*)(b + c);
    float4 o;
    o.x = (xv.x - mean) * rstd * gv.x + bv.x;
    o.y = (xv.y - mean) * rstd * gv.y + bv.y;
    o.z = (xv.z - mean) * rstd * gv.z + bv.z;
    o.w = (xv.w - mean) * rstd * gv.w + bv.w;
    split4_store(o, yh + (size_t)row * C_ + c, yl + (size_t)row * C_ + c);
}

__global__ void layernorm_last_kernel(const float* __restrict__ x,
                                      const float* __restrict__ g,
                                      const float* __restrict__ b,
                                      float* __restrict__ y) {
    int row_in  = blockIdx.x * T_ + (T_ - 1);
    int tid = threadIdx.x;
    int c = tid * 4;

    float4 xv = *(const float4*)(x + (size_t)row_in * C_ + c);
    float s  = xv.x + xv.y + xv.z + xv.w;
    float sq = xv.x*xv.x + xv.y*xv.y + xv.z*xv.z + xv.w*xv.w;

    __shared__ float ssum[256];
    __shared__ float ssq[256];
    ssum[tid] = s; ssq[tid] = sq;
    __syncthreads();
    #pragma unroll
    for (int st = 128; st > 0; st >>= 1) {
        if (tid < st) { ssum[tid] += ssum[tid+st]; ssq[tid] += ssq[tid+st]; }
        __syncthreads();
    }
    __shared__ float s_mean, s_rstd;
    if (tid == 0) {
        float mean = ssum[0] * (1.0f / C_);
        float var  = ssq[0] * (1.0f / C_) - mean * mean;
        s_mean = mean;
        s_rstd = rsqrtf(var + 1e-5f);
    }
    __syncthreads();
    float mean = s_mean, rstd = s_rstd;

    float4 gv = *(const float4*)(g + c);
    float4 bv = *(const float4*)(b + c);
    float4 o;
    o.x = (xv.x - mean) * rstd * gv.x + bv.x;
    o.y = (xv.y - mean) * rstd * gv.y + bv.y;
    o.z = (xv.z - mean) * rstd * gv.z + bv.z;
    o.w = (xv.w - mean) * rstd * gv.w + bv.w;
    *(float4*)(y + (size_t)blockIdx.x * C_ + c) = o;
}

// ===========================================================================
// mma.sync split-bf16 GEMM (256 threads, BM template, MI=BM/32).
// VFUSE: columns n >= 2048 written transposed+split into vth/vtl.
// ===========================================================================
#define SWZ(row, chunk) ((((chunk) ^ ((row) & 7)) << 4) + (row) * 128)
#define GEMM_SMEM 196608

template<int ROWS>
__device__ __forceinline__ void load_tile_cp(const __nv_bfloat16* __restrict__ src,
                                             int row0, int K, int kt,
                                             uint32_t sbase, int tid) {
    #pragma unroll
    for (int r = 0; r < ROWS / 32; r++) {
        int cid = tid + r * 256;
        int row = cid >> 3;
        int c   = cid & 7;
        const __nv_bfloat16* g = src + (size_t)(row0 + row) * K + kt * 64 + c * 8;
        CP_ASYNC16(sbase + SWZ(row, c), g);
    }
}

template<int BM, bool RELU, bool RES, bool OUTBF16, bool VFUSE>
__global__ __launch_bounds__(256, 1)
void gemm_tc(const __nv_bfloat16* __restrict__ Ah, const __nv_bfloat16* __restrict__ Al,
             const __nv_bfloat16* __restrict__ Bh, const __nv_bfloat16* __restrict__ Bl,
             const float* __restrict__ bias, const float* __restrict__ res,
             float* __restrict__ Cf,
             __nv_bfloat16* __restrict__ Ch, __nv_bfloat16* __restrict__ Cl,
             __nv_bfloat16* __restrict__ vth, __nv_bfloat16* __restrict__ vtl,
             int M, int N, int K) {
    constexpr int MI      = BM / 32;
    constexpr int A_TILE  = BM * 128;
    constexpr int B_TILE  = 16384;
    constexpr int STG     = (BM == 128) ? 3 : 2;
    constexpr int STAGE   = 2 * A_TILE + 2 * B_TILE;

    extern __shared__ char dsm[];
    const uint32_t base = smem_u32(dsm);

    const int tid  = threadIdx.x;
    const int wid  = tid >> 5;
    const int lane = tid & 31;
    const int m0 = blockIdx.y * BM;
    const int n0 = blockIdx.x * 128;
    const int wm = wid & 1;
    const int wn = wid >> 1;

    float acc[MI][4][4];
    #pragma unroll
    for (int i = 0; i < MI; i++)
        #pragma unroll
        for (int j = 0; j < 4; j++)
            #pragma unroll
            for (int r = 0; r < 4; r++) acc[i][j][r] = 0.0f;

    const int nkt = K >> 6;

    const int a_row  = wm * (BM / 2) + (lane & 15);
    const int a_csel = lane >> 4;
    const int b_row  = wn * 32 + ((lane & 7) | ((lane & 16) >> 1));
    const int b_csel = (lane >> 3) & 1;

    {
        load_tile_cp<BM>(Ah, m0, K, 0, base, tid);
        load_tile_cp<BM>(Al, m0, K, 0, base + A_TILE, tid);
        load_tile_cp<128>(Bh, n0, K, 0, base + 2 * A_TILE, tid);
        load_tile_cp<128>(Bl, n0, K, 0, base + 2 * A_TILE + B_TILE, tid);
        CP_COMMIT();
        load_tile_cp<BM>(Ah, m0, K, 1, base + STAGE, tid);
        load_tile_cp<BM>(Al, m0, K, 1, base + STAGE + A_TILE, tid);
        load_tile_cp<128>(Bh, n0, K, 1, base + STAGE + 2 * A_TILE, tid);
        load_tile_cp<128>(Bl, n0, K, 1, base + STAGE + 2 * A_TILE + B_TILE, tid);
        CP_COMMIT();
    }

    for (int kt = 0; kt < nkt; kt++) {
        if (kt + 1 < nkt) { CP_WAIT1(); } else { CP_WAIT0(); }
        __syncthreads();

        if (STG == 3 && kt + 2 < nkt) {
            const uint32_t nb = base + ((kt + 2) % 3) * STAGE;
            load_tile_cp<BM>(Ah, m0, K, kt + 2, nb, tid);
            load_tile_cp<BM>(Al, m0, K, kt + 2, nb + A_TILE, tid);
            load_tile_cp<128>(Bh, n0, K, kt + 2, nb + 2 * A_TILE, tid);
            load_tile_cp<128>(Bl, n0, K, kt + 2, nb + 2 * A_TILE + B_TILE, tid);
            CP_COMMIT();
        }

        const uint32_t sb  = base + (kt % STG) * STAGE;
        const uint32_t sAh = sb;
        const uint32_t sAl = sb + A_TILE;
        const uint32_t sBh = sb + 2 * A_TILE;
        const uint32_t sBl = sb + 2 * A_TILE + B_TILE;

        #pragma unroll
        for (int ks = 0; ks < 4; ks++) {
            const int ac = ks * 2 + a_csel;
            const int bc = ks * 2 + b_csel;
            uint32_t bh[4][2], bl[4][2];
            #pragma unroll
            for (int nj = 0; nj < 2; nj++) {
                int row = b_row + nj * 16;
                ldm_x4(sBh + SWZ(row, bc), bh[nj*2][0], bh[nj*2][1], bh[nj*2+1][0], bh[nj*2+1][1]);
                ldm_x4(sBl + SWZ(row, bc), bl[nj*2][0], bl[nj*2][1], bl[nj*2+1][0], bl[nj*2+1][1]);
            }
            #pragma unroll
            for (int mi = 0; mi < MI; mi++) {
                uint32_t ah0, ah1, ah2, ah3, al0, al1, al2, al3;
                int row = a_row + mi * 16;
                ldm_x4(sAh + SWZ(row, ac), ah0, ah1, ah2, ah3);
                ldm_x4(sAl + SWZ(row, ac), al0, al1, al2, al3);
                #pragma unroll
                for (int ni = 0; ni < 4; ni++) {
                    mma_bf16(acc[mi][ni][0], acc[mi][ni][1], acc[mi][ni][2], acc[mi][ni][3],
                             ah0, ah1, ah2, ah3, bh[ni][0], bh[ni][1]);
                    mma_bf16(acc[mi][ni][0], acc[mi][ni][1], acc[mi][ni][2], acc[mi][ni][3],
                             ah0, ah1, ah2, ah3, bl[ni][0], bl[ni][1]);
                    mma_bf16(acc[mi][ni][0], acc[mi][ni][1], acc[mi][ni][2], acc[mi][ni][3],
                             al0, al1, al2, al3, bh[ni][0], bh[ni][1]);
                }
            }
        }

        if (STG == 2) {
            __syncthreads();
            if (kt + 2 < nkt) {
                const uint32_t nb = base + (kt & 1) * STAGE;
                load_tile_cp<BM>(Ah, m0, K, kt + 2, nb, tid);
                load_tile_cp<BM>(Al, m0, K, kt + 2, nb + A_TILE, tid);
                load_tile_cp<128>(Bh, n0, K, kt + 2, nb + 2 * A_TILE, tid);
                load_tile_cp<128>(Bl, n0, K, kt + 2, nb + 2 * A_TILE + B_TILE, tid);
                CP_COMMIT();
            }
        }
    }

    const int qm = lane >> 2;
    const int qn = (lane & 3) * 2;
    const bool vblock = VFUSE && (n0 >= 2 * C_);
    #pragma unroll
    for (int mi = 0; mi < MI; mi++) {
        #pragma unroll
        for (int ni = 0; ni < 4; ni++) {
            const int n = n0 + wn * 32 + ni * 8 + qn;
            float2 bv = *(const float2*)(bias + n);
            #pragma unroll
            for (int half = 0; half < 2; half++) {
                const int m = m0 + wm * (BM / 2) + mi * 16 + qm + half * 8;
                float vx = acc[mi][ni][half*2 + 0] + bv.x;
                float vy = acc[mi][ni][half*2 + 1] + bv.y;
                if (RELU) { vx = fmaxf(vx, 0.f); vy = fmaxf(vy, 0.f); }
                if (RES) {
                    float2 rv = *(const float2*)(res + (size_t)m * N + n);
                    vx += rv.x; vy += rv.y;
                }
                if (vblock) {
                    const int t  = m & (T_ - 1);
                    const int bb = m >> 11;
                    const int nv = n - 2 * C_;
                    const int hh = nv >> 6;
                    const int d  = nv & 63;
                    __nv_bfloat16 h0, l0, h1, l1;
                    split1(vx, h0, l0);
                    split1(vy, h1, l1);
                    size_t vo = ((size_t)(bb * H_ + hh) * 64 + d) * T_ + t;
                    vth[vo]      = h0;
                    vth[vo + T_] = h1;
                    vtl[vo]      = l0;
                    vtl[vo + T_] = l1;
                } else if (OUTBF16) {
                    split2_store(vx, vy, Ch + (size_t)m * N + n, Cl + (size_t)m * N + n);
                } else {
                    *(float2*)(Cf + (size_t)m * N + n) = make_float2(vx, vy);
                }
            }
        }
    }
}

// ===========================================================================
// Tensor-core flash attention (64 queries/CTA, 4 warps)
// ===========================================================================
#define ATT_SMEM (16384 + 32768)

__global__ __launch_bounds__(128)
void attention_mma_kernel(const __nv_bfloat16* __restrict__ qkvh,
                          const __nv_bfloat16* __restrict__ qkvl,
                          const __nv_bfloat16* __restrict__ Vth,
                          const __nv_bfloat16* __restrict__ Vtl,
                          __nv_bfloat16* __restrict__ aoh,
                          __nv_bfloat16* __restrict__ aol) {
    extern __shared__ char dsm[];
    const uint32_t base = smem_u32(dsm);
    const uint32_t sQh = base;
    const uint32_t sQl = base + 8192;
    const uint32_t sKh = base + 16384;
    const uint32_t sKl = base + 24576;
    const uint32_t sVh = base + 32768;
    const uint32_t sVl = base + 40960;

    const int b  = blockIdx.z;
    const int h  = blockIdx.y;
    const int qt = (T_ / 64 - 1) - blockIdx.x;
    const int tid  = threadIdx.x;
    const int wid  = tid >> 5;
    const int lane = tid & 31;
    const int m_base = wid * 16;

    #pragma unroll
    for (int r = 0; r < 4; r++) {
        int cid = tid + r * 128;
        int row = cid >> 3;
        int c   = cid & 7;
        size_t goff = (size_t)(b * T_ + qt * 64 + row) * QKV_ + h * 64 + c * 8;
        CP_ASYNC16(sQh + SWZ(row, c), qkvh + goff);
        CP_ASYNC16(sQl + SWZ(row, c), qkvl + goff);
    }
    CP_COMMIT(); CP_WAIT0();
    __syncthreads();

    const int a_row  = m_base + (lane & 15);
    const int a_csel = lane >> 4;
    uint32_t qfh[4][4], qfl[4][4];
    #pragma unroll
    for (int ks = 0; ks < 4; ks++) {
        ldm_x4(sQh + SWZ(a_row, ks*2 + a_csel), qfh[ks][0], qfh[ks][1], qfh[ks][2], qfh[ks][3]);
        ldm_x4(sQl + SWZ(a_row, ks*2 + a_csel), qfl[ks][0], qfl[ks][1], qfl[ks][2], qfl[ks][3]);
    }

    const int b_row_l = (lane & 7) | ((lane & 16) >> 1);
    const int b_csel  = (lane >> 3) & 1;
    const int qm = lane >> 2;
    const int qn = (lane & 3) * 2;

    float o[8][4];
    #pragma unroll
    for (int n = 0; n < 8; n++)
        #pragma unroll
        for (int r = 0; r < 4; r++) o[n][r] = 0.0f;
    float mrow[2] = {-FLT_MAX, -FLT_MAX};
    float lrow[2] = {0.0f, 0.0f};

    for (int kt = 0; kt <= qt; kt++) {
        __syncthreads();
        #pragma unroll
        for (int r = 0; r < 4; r++) {
            int cid = tid + r * 128;
            int row = cid >> 3;
            int c   = cid & 7;
            size_t koff = (size_t)(b * T_ + kt * 64 + row) * QKV_ + C_ + h * 64 + c * 8;
            size_t voff = ((size_t)(b * H_ + h) * 64 + row) * T_ + kt * 64 + c * 8;
            CP_ASYNC16(sKh + SWZ(row, c), qkvh + koff);
            CP_ASYNC16(sKl + SWZ(row, c), qkvl + koff);
            CP_ASYNC16(sVh + SWZ(row, c), Vth + voff);
            CP_ASYNC16(sVl + SWZ(row, c), Vtl + voff);
        }
        CP_COMMIT(); CP_WAIT0();
        __syncthreads();

        float sc[8][4];
        #pragma unroll
        for (int n = 0; n < 8; n++)
            #pragma unroll
            for (int r = 0; r < 4; r++) sc[n][r] = 0.0f;

        #pragma unroll
        for (int ks = 0; ks < 4; ks++) {
            const int bc = ks * 2 + b_csel;
            #pragma unroll
            for (int g = 0; g < 4; g++) {
                uint32_t r0, r1, r2, r3, s0, s1, s2, s3;
                ldm_x4(sKh + SWZ(g * 16 + b_row_l, bc), r0, r1, r2, r3);
                ldm_x4(sKl + SWZ(g * 16 + b_row_l, bc), s0, s1, s2, s3);
                mma_bf16(sc[2*g][0], sc[2*g][1], sc[2*g][2], sc[2*g][3],
                         qfh[ks][0], qfh[ks][1], qfh[ks][2], qfh[ks][3], r0, r1);
                mma_bf16(sc[2*g+1][0], sc[2*g+1][1], sc[2*g+1][2], sc[2*g+1][3],
                         qfh[ks][0], qfh[ks][1], qfh[ks][2], qfh[ks][3], r2, r3);
                mma_bf16(sc[2*g][0], sc[2*g][1], sc[2*g][2], sc[2*g][3],
                         qfh[ks][0], qfh[ks][1], qfh[ks][2], qfh[ks][3], s0, s1);
                mma_bf16(sc[2*g+1][0], sc[2*g+1][1], sc[2*g+1][2], sc[2*g+1][3],
                         qfh[ks][0], qfh[ks][1], qfh[ks][2], qfh[ks][3], s2, s3);
                mma_bf16(sc[2*g][0], sc[2*g][1], sc[2*g][2], sc[2*g][3],
                         qfl[ks][0], qfl[ks][1], qfl[ks][2], qfl[ks][3], r0, r1);
                mma_bf16(sc[2*g+1][0], sc[2*g+1][1], sc[2*g+1][2], sc[2*g+1][3],
                         qfl[ks][0], qfl[ks][1], qfl[ks][2], qfl[ks][3], r2, r3);
            }
        }

        #pragma unroll
        for (int n = 0; n < 8; n++)
            #pragma unroll
            for (int r = 0; r < 4; r++) sc[n][r] *= 0.125f;

        if (kt == qt) {
            const int row0 = m_base + qm;
            const int row1 = row0 + 8;
            #pragma unroll
            for (int n = 0; n < 8; n++) {
                int col = n * 8 + qn;
                if (col     > row0) sc[n][0] = -FLT_MAX;
                if (col + 1 > row0) sc[n][1] = -FLT_MAX;
                if (col     > row1) sc[n][2] = -FLT_MAX;
                if (col + 1 > row1) sc[n][3] = -FLT_MAX;
            }
        }

        #pragma unroll
        for (int r = 0; r < 2; r++) {
            float mx = -FLT_MAX;
            #pragma unroll
            for (int n = 0; n < 8; n++) {
                mx = fmaxf(mx, sc[n][2*r]);
                mx = fmaxf(mx, sc[n][2*r + 1]);
            }
            mx = fmaxf(mx, __shfl_xor_sync(0xffffffffu, mx, 1));
            mx = fmaxf(mx, __shfl_xor_sync(0xffffffffu, mx, 2));
            float mnew = fmaxf(mrow[r], mx);
            float alpha = __expf(mrow[r] - mnew);
            float sum = 0.0f;
            #pragma unroll
            for (int n = 0; n < 8; n++) {
                float p0 = __expf(sc[n][2*r]     - mnew);
                float p1 = __expf(sc[n][2*r + 1] - mnew);
                sc[n][2*r]     = p0;
                sc[n][2*r + 1] = p1;
                sum += p0 + p1;
            }
            sum += __shfl_xor_sync(0xffffffffu, sum, 1);
            sum += __shfl_xor_sync(0xffffffffu, sum, 2);
            lrow[r] = lrow[r] * alpha + sum;
            mrow[r] = mnew;
            #pragma unroll
            for (int n = 0; n < 8; n++) {
                o[n][2*r]     *= alpha;
                o[n][2*r + 1] *= alpha;
            }
        }

        #pragma unroll
        for (int ks = 0; ks < 4; ks++) {
            uint32_t ph0, ph1, ph2, ph3, pl0, pl1, pl2, pl3;
            pack_split(sc[2*ks][0],   sc[2*ks][1],   ph0, pl0);
            pack_split(sc[2*ks][2],   sc[2*ks][3],   ph1, pl1);
            pack_split(sc[2*ks+1][0], sc[2*ks+1][1], ph2, pl2);
            pack_split(sc[2*ks+1][2], sc[2*ks+1][3], ph3, pl3);
            const int bc = ks * 2 + b_csel;
            #pragma unroll
            for (int g = 0; g < 4; g++) {
                uint32_t r0, r1, r2, r3, s0, s1, s2, s3;
                ldm_x4(sVh + SWZ(g * 16 + b_row_l, bc), r0, r1, r2, r3);
                ldm_x4(sVl + SWZ(g * 16 + b_row_l, bc), s0, s1, s2, s3);
                mma_bf16(o[2*g][0], o[2*g][1], o[2*g][2], o[2*g][3],
                         ph0, ph1, ph2, ph3, r0, r1);
                mma_bf16(o[2*g+1][0], o[2*g+1][1], o[2*g+1][2], o[2*g+1][3],
                         ph0, ph1, ph2, ph3, r2, r3);
                mma_bf16(o[2*g][0], o[2*g][1], o[2*g][2], o[2*g][3],
                         ph0, ph1, ph2, ph3, s0, s1);
                mma_bf16(o[2*g+1][0], o[2*g+1][1], o[2*g+1][2], o[2*g+1][3],
                         ph0, ph1, ph2, ph3, s2, s3);
                mma_bf16(o[2*g][0], o[2*g][1], o[2*g][2], o[2*g][3],
                         pl0, pl1, pl2, pl3, r0, r1);
                mma_bf16(o[2*g+1][0], o[2*g+1][1], o[2*g+1][2], o[2*g+1][3],
                         pl0, pl1, pl2, pl3, r2, r3);
            }
        }
    }

    const float inv0 = 1.0f / lrow[0];
    const float inv1 = 1.0f / lrow[1];
    const size_t row0 = (size_t)(b * T_ + qt * 64 + m_base + qm) * C_;
    const size_t row1 = row0 + 8 * C_;
    #pragma unroll
    for (int n = 0; n < 8; n++) {
        int col = h * 64 + n * 8 + qn;
        split2_store(o[n][0] * inv0, o[n][1] * inv0, aoh + row0 + col, aol + row0 + col);
        split2_store(o[n][2] * inv1, o[n][3] * inv1, aoh + row1 + col, aol + row1 + col);
    }
}

// ===========================================================================
// Logits (per-batch blocks, R8 version)
// ===========================================================================
__global__ void logits_kernel(const float* __restrict__ xf,
                              const float* __restrict__ W,
                              const float* __restrict__ bias,
                              float* __restrict__ out) {
    __shared__ float xs[C_];
    const int b = blockIdx.y;
    const int tid = threadIdx.x;
    #pragma unroll
    for (int r = 0; r < C_ / 128; r++)
        xs[tid + r * 128] = xf[b * C_ + tid + r * 128];
    __syncthreads();

    int vcol = blockIdx.x * 128 + tid;
    float acc = bias[vcol];
    const float* wp = W + vcol;
    #pragma unroll 8
    for (int k = 0; k < C_; k++)
        acc = fmaf(xs[k], wp[(size_t)k * V_], acc);
    out[(size_t)b * V_ + vcol] = acc;
}

// ===========================================================================
// Launch (R8 structure exactly)
// ===========================================================================
extern "C" void kernel_launch(void* const* d_in, const int* in_sizes, int n_in,
                              void* d_out, int out_size) {
    const int*   idx   = (const int*)  d_in[0];
    const float* emb   = (const float*)d_in[1];
    const float* pos   = (const float*)d_in[2];
    const float* ln1_g = (const float*)d_in[3];
    const float* ln1_b = (const float*)d_in[4];
    const float* wq    = (const float*)d_in[5];
    const float* bq    = (const float*)d_in[6];
    const float* wk    = (const float*)d_in[7];
    const float* bk    = (const float*)d_in[8];
    const float* wv    = (const float*)d_in[9];
    const float* bv    = (const float*)d_in[10];
    const float* wo    = (const float*)d_in[11];
    const float* bo    = (const float*)d_in[12];
    const float* ln2_g = (const float*)d_in[13];
    const float* ln2_b = (const float*)d_in[14];
    const float* w1    = (const float*)d_in[15];
    const float* b1    = (const float*)d_in[16];
    const float* w2    = (const float*)d_in[17];
    const float* b2    = (const float*)d_in[18];
    const float* lnf_g = (const float*)d_in[19];
    const float* lnf_b = (const float*)d_in[20];
    const float* out_w = (const float*)d_in[21];
    const float* out_b = (const float*)d_in[22];
    float* out = (float*)d_out;

    float *x, *xf, *bqkv;
    cudaGetSymbolAddress((void**)&x,    g_x);
    cudaGetSymbolAddress((void**)&xf,   g_xf);
    cudaGetSymbolAddress((void**)&bqkv, g_bqkv);

    __nv_bfloat16 *h_h, *h_l, *qkvh, *qkvl, *vth, *vtl, *ao_h, *ao_l, *hid_h, *hid_l;
    cudaGetSymbolAddress((void**)&h_h,   g_h_h);
    cudaGetSymbolAddress((void**)&h_l,   g_h_l);
    cudaGetSymbolAddress((void**)&qkvh,  g_qkvh);
    cudaGetSymbolAddress((void**)&qkvl,  g_qkvl);
    cudaGetSymbolAddress((void**)&vth,   g_vth);
    cudaGetSymbolAddress((void**)&vtl,   g_vtl);
    cudaGetSymbolAddress((void**)&ao_h,  g_ao_h);
    cudaGetSymbolAddress((void**)&ao_l,  g_ao_l);
    cudaGetSymbolAddress((void**)&hid_h, g_hid_h);
    cudaGetSymbolAddress((void**)&hid_l, g_hid_l);

    __nv_bfloat16 *wqkvT_h, *wqkvT_l, *woT_h, *woT_l, *w1T_h, *w1T_l, *w2T_h, *w2T_l;
    cudaGetSymbolAddress((void**)&wqkvT_h, g_wqkvT_h);
    cudaGetSymbolAddress((void**)&wqkvT_l, g_wqkvT_l);
    cudaGetSymbolAddress((void**)&woT_h, g_woT_h);
    cudaGetSymbolAddress((void**)&woT_l, g_woT_l);
    cudaGetSymbolAddress((void**)&w1T_h, g_w1T_h);
    cudaGetSymbolAddress((void**)&w1T_l, g_w1T_l);
    cudaGetSymbolAddress((void**)&w2T_h, g_w2T_h);
    cudaGetSymbolAddress((void**)&w2T_l, g_w2T_l);

    cudaFuncSetAttribute(gemm_tc<256, false, false, true, true>,
                         cudaFuncAttributeMaxDynamicSharedMemorySize, GEMM_SMEM);
    cudaFuncSetAttribute(gemm_tc<128, true, false, true, false>,
                         cudaFuncAttributeMaxDynamicSharedMemorySize, GEMM_SMEM);
    cudaFuncSetAttribute(gemm_tc<256, false, true, false, false>,
                         cudaFuncAttributeMaxDynamicSharedMemorySize, GEMM_SMEM);
    cudaFuncSetAttribute(attention_mma_kernel,
                         cudaFuncAttributeMaxDynamicSharedMemorySize, ATT_SMEM);

    // Weight prep: 3 launches
    {
        dim3 blk(32, 8);
        transpose_split_qkv_kernel<<<dim3(32, 32, 24), blk>>>(wq, wk, wv, wqkvT_h, wqkvT_l);
        transpose_split_wo_w2_kernel<<<dim3(32, 160, 8), blk>>>(wo, w2, woT_h, woT_l, w2T_h, w2T_l);
        transpose_split_kernel<<<dim3(128, 32, 8), blk>>>(w1, w1T_h, w1T_l, C_, F_, (size_t)C_ * F_);
    }

    embed_kernel<<<BT_, 256>>>(idx, emb, pos, bq, bk, bv, x, bqkv);

    dim3 gemm_qkv(QKV_ / 128, BT_ / 256);  // (24, 16)  BM=256, V fused-transposed
    dim3 gemm_cc(C_ / 128, BT_ / 256);     // (8, 16)   BM=256
    dim3 gemm_cf(F_ / 128, BT_ / 128);     // (32, 32)  BM=128
    dim3 attn_grid(T_ / 64, H_, B_);

    for (int l = 0; l < L_; l++) {
        layernorm_bf16_kernel<<<BT_, 256>>>(x, ln1_g + l * C_, ln1_b + l * C_, h_h, h_l);

        // merged QKV projection; V columns written straight into vt layout
        gemm_tc<256, false, false, true, true><<<gemm_qkv, 256, GEMM_SMEM>>>(
            h_h, h_l, wqkvT_h + (size_t)l * QKV_ * C_, wqkvT_l + (size_t)l * QKV_ * C_,
            bqkv + l * QKV_, nullptr, nullptr, qkvh, qkvl, vth, vtl, BT_, QKV_, C_);

        attention_mma_kernel<<<attn_grid, 128, ATT_SMEM>>>(
            qkvh, qkvl, vth, vtl, ao_h, ao_l);

        // x = x + (ao @ wo + bo)
        gemm_tc<256, false, true, false, false><<<gemm_cc, 256, GEMM_SMEM>>>(
            ao_h, ao_l, woT_h + (size_t)l * C_ * C_, woT_l + (size_t)l * C_ * C_,
            bo + l * C_, x, x, nullptr, nullptr, nullptr, nullptr, BT_, C_, C_);

        layernorm_bf16_kernel<<<BT_, 256>>>(x, ln2_g + l * C_, ln2_b + l * C_, h_h, h_l);

        // hid = relu(h @ w1 + b1)
        gemm_tc<128, true, false, true, false><<<gemm_cf, 256, GEMM_SMEM>>>(
            h_h, h_l, w1T_h + (size_t)l * C_ * F_, w1T_l + (size_t)l * C_ * F_,
            b1 + l * F_, nullptr, nullptr, hid_h, hid_l, nullptr, nullptr, BT_, F_, C_);
        // x = x + (hid @ w2 + b2)
        gemm_tc<256, false, true, false, false><<<gemm_cc, 256, GEMM_SMEM>>>(
            hid_h, hid_l, w2T_h + (size_t)l * F_ * C_, w2T_l + (size_t)l * F_ * C_,
            b2 + l * C_, x, x, nullptr, nullptr, nullptr, nullptr, BT_, C_, F_);
    }

    layernorm_last_kernel<<<B_, 256>>>(x, lnf_g, lnf_b, xf);
    logits_kernel<<<dim3(V_ / 128, B_), 128>>>(xf, out_w, out_b, out);
}

// round 16
// speedup vs baseline: 1.0290x; 1.0021x over previous
#include <cuda_runtime.h>
#include <cuda_bf16.h>
#include <float.h>
#include <cstdint>

// Problem constants
#define V_   32000
#define C_   1024
#define H_   16
#define L_   8
#define F_   4096
#define B_   2
#define T_   2048
#define D_   64
#define BT_  (B_*T_)
#define QKV_ (3*C_)

// ===========================================================================
// helpers
// ===========================================================================
__device__ __forceinline__ uint32_t smem_u32(const void* p) {
    uint32_t a;
    asm("{ .reg .u64 t; cvta.to.shared.u64 t, %1; cvt.u32.u64 %0, t; }"
        : "=r"(a) : "l"(p));
    return a;
}

#define CP_ASYNC16(saddr, gptr) \
    asm volatile("cp.async.cg.shared.global [%0], [%1], 16;" \
                 :: "r"(saddr), "l"(gptr) : "memory")
#define CP_COMMIT() asm volatile("cp.async.commit_group;" ::: "memory")
#define CP_WAIT1()  asm volatile("cp.async.wait_group 1;" ::: "memory")
#define CP_WAIT0()  asm volatile("cp.async.wait_group 0;" ::: "memory")

__device__ __forceinline__ void ldm_x4(uint32_t addr, uint32_t& r0, uint32_t& r1,
                                       uint32_t& r2, uint32_t& r3) {
    asm volatile("ldmatrix.sync.aligned.m8n8.x4.shared.b16 {%0,%1,%2,%3}, [%4];"
                 : "=r"(r0), "=r"(r1), "=r"(r2), "=r"(r3) : "r"(addr));
}

__device__ __forceinline__ void mma_bf16(float& d0, float& d1, float& d2, float& d3,
                                         uint32_t a0, uint32_t a1, uint32_t a2, uint32_t a3,
                                         uint32_t b0, uint32_t b1) {
    asm volatile(
        "mma.sync.aligned.m16n8k16.row.col.f32.bf16.bf16.f32 "
        "{%0,%1,%2,%3}, {%4,%5,%6,%7}, {%8,%9}, {%0,%1,%2,%3};"
        : "+f"(d0), "+f"(d1), "+f"(d2), "+f"(d3)
        : "r"(a0), "r"(a1), "r"(a2), "r"(a3), "r"(b0), "r"(b1));
}

// bf16 hi/lo split helpers
__device__ __forceinline__ void split1(float v, __nv_bfloat16& h, __nv_bfloat16& l) {
    h = __float2bfloat16(v);
    l = __float2bfloat16(v - __bfloat162float(h));
}
__device__ __forceinline__ void split2_store(float x, float y,
                                             __nv_bfloat16* ph, __nv_bfloat16* pl) {
    __nv_bfloat16 h0, h1, l0, l1;
    split1(x, h0, l0); split1(y, h1, l1);
    __nv_bfloat162 H; H.x = h0; H.y = h1;
    __nv_bfloat162 L; L.x = l0; L.y = l1;
    *(__nv_bfloat162*)ph = H;
    *(__nv_bfloat162*)pl = L;
}
__device__ __forceinline__ void split4_store(float4 v, __nv_bfloat16* ph, __nv_bfloat16* pl) {
    split2_store(v.x, v.y, ph, pl);
    split2_store(v.z, v.w, ph + 2, pl + 2);
}
__device__ __forceinline__ void pack_split(float x, float y, uint32_t& hi, uint32_t& lo) {
    __nv_bfloat16 hx, lx, hy, ly;
    split1(x, hx, lx); split1(y, hy, ly);
    __nv_bfloat162 Hh; Hh.x = hx; Hh.y = hy;
    __nv_bfloat162 Ll; Ll.x = lx; Ll.y = ly;
    hi = *reinterpret_cast<uint32_t*>(&Hh);
    lo = *reinterpret_cast<uint32_t*>(&Ll);
}

// ===========================================================================
// Scratch
// ===========================================================================
__device__ float g_x  [BT_ * C_];
__device__ float g_xf [B_ * C_];
__device__ float g_bqkv[L_ * QKV_];

__device__ __nv_bfloat16 g_h_h  [BT_ * C_];
__device__ __nv_bfloat16 g_h_l  [BT_ * C_];
__device__ __nv_bfloat16 g_qkvh [(size_t)BT_ * QKV_];
__device__ __nv_bfloat16 g_qkvl [(size_t)BT_ * QKV_];
__device__ __nv_bfloat16 g_vth  [B_ * H_ * D_ * T_];
__device__ __nv_bfloat16 g_vtl  [B_ * H_ * D_ * T_];
__device__ __nv_bfloat16 g_ao_h [BT_ * C_];
__device__ __nv_bfloat16 g_ao_l [BT_ * C_];
__device__ __nv_bfloat16 g_hid_h[BT_ * F_];
__device__ __nv_bfloat16 g_hid_l[BT_ * F_];

__device__ __nv_bfloat16 g_wqkvT_h[(size_t)L_ * QKV_ * C_];
__device__ __nv_bfloat16 g_wqkvT_l[(size_t)L_ * QKV_ * C_];
__device__ __nv_bfloat16 g_woT_h[L_ * C_ * C_];
__device__ __nv_bfloat16 g_woT_l[L_ * C_ * C_];
__device__ __nv_bfloat16 g_w1T_h[L_ * C_ * F_];
__device__ __nv_bfloat16 g_w1T_l[L_ * C_ * F_];
__device__ __nv_bfloat16 g_w2T_h[L_ * F_ * C_];
__device__ __nv_bfloat16 g_w2T_l[L_ * F_ * C_];

// ===========================================================================
// Embedding (+ QKV bias concat)
// ===========================================================================
__global__ void embed_kernel(const int* __restrict__ idx,
                             const float* __restrict__ emb,
                             const float* __restrict__ pos,
                             const float* __restrict__ bq,
                             const float* __restrict__ bk,
                             const float* __restrict__ bv,
                             float* __restrict__ x,
                             float* __restrict__ bqkv) {
    int row = blockIdx.x;
    int t   = row % T_;
    int tok = idx[row];
    int c   = threadIdx.x * 4;
    float4 e = *(const float4*)(emb + (size_t)tok * C_ + c);
    float4 p = *(const float4*)(pos + (size_t)t   * C_ + c);
    float4 o;
    o.x = e.x + p.x; o.y = e.y + p.y; o.z = e.z + p.z; o.w = e.w + p.w;
    *(float4*)(x + (size_t)row * C_ + c) = o;

    if (blockIdx.x < (L_ * QKV_) / 256) {
        int i = blockIdx.x * 256 + threadIdx.x;
        int layer = i / QKV_;
        int col   = i % QKV_;
        float v;
        if (col < C_)           v = bq[layer * C_ + col];
        else if (col < 2 * C_)  v = bk[layer * C_ + col - C_];
        else                    v = bv[layer * C_ + col - 2 * C_];
        bqkv[i] = v;
    }
}

// ===========================================================================
// Weight transposes + bf16 split — 3 launches.
// ===========================================================================
__global__ void transpose_split_kernel(const float* __restrict__ in,
                                       __nv_bfloat16* __restrict__ oh,
                                       __nv_bfloat16* __restrict__ ol,
                                       int K, int N, size_t out_lstride) {
    __shared__ float t[32][33];
    const float* inl = in + (size_t)blockIdx.z * K * N;
    const size_t obase = (size_t)blockIdx.z * out_lstride;
    const int k0 = blockIdx.y * 32;
    const int n0 = blockIdx.x * 32;
    #pragma unroll
    for (int j = 0; j < 4; j++) {
        int k = k0 + threadIdx.y + j * 8;
        t[threadIdx.y + j * 8][threadIdx.x] = inl[(size_t)k * N + n0 + threadIdx.x];
    }
    __syncthreads();
    #pragma unroll
    for (int j = 0; j < 4; j++) {
        int n = n0 + threadIdx.y + j * 8;
        float v = t[threadIdx.x][threadIdx.y + j * 8];
        __nv_bfloat16 h, l;
        split1(v, h, l);
        size_t off = obase + (size_t)n * K + k0 + threadIdx.x;
        oh[off] = h;
        ol[off] = l;
    }
}

__global__ void transpose_split_qkv_kernel(const float* __restrict__ wq,
                                           const float* __restrict__ wk,
                                           const float* __restrict__ wv,
                                           __nv_bfloat16* __restrict__ oh,
                                           __nv_bfloat16* __restrict__ ol) {
    __shared__ float t[32][33];
    const int z = blockIdx.z;
    const int layer = z & 7;
    const int which = z >> 3;
    const float* in = (which == 0 ? wq : which == 1 ? wk : wv) + (size_t)layer * C_ * C_;
    const size_t obase = (size_t)layer * QKV_ * C_ + (size_t)which * C_ * C_;
    const int k0 = blockIdx.y * 32;
    const int n0 = blockIdx.x * 32;
    #pragma unroll
    for (int j = 0; j < 4; j++) {
        int k = k0 + threadIdx.y + j * 8;
        t[threadIdx.y + j * 8][threadIdx.x] = in[(size_t)k * C_ + n0 + threadIdx.x];
    }
    __syncthreads();
    #pragma unroll
    for (int j = 0; j < 4; j++) {
        int n = n0 + threadIdx.y + j * 8;
        float v = t[threadIdx.x][threadIdx.y + j * 8];
        __nv_bfloat16 h, l;
        split1(v, h, l);
        size_t off = obase + (size_t)n * C_ + k0 + threadIdx.x;
        oh[off] = h;
        ol[off] = l;
    }
}

__global__ void transpose_split_wo_w2_kernel(const float* __restrict__ wo,
                                             const float* __restrict__ w2,
                                             __nv_bfloat16* __restrict__ ooh,
                                             __nv_bfloat16* __restrict__ ool,
                                             __nv_bfloat16* __restrict__ o2h,
                                             __nv_bfloat16* __restrict__ o2l) {
    __shared__ float t[32][33];
    const int layer = blockIdx.z;
    const bool isW2 = (blockIdx.y >= 32);
    const float* in;
    __nv_bfloat16 *oh, *ol;
    int K, k0;
    size_t obase;
    if (!isW2) {
        in = wo + (size_t)layer * C_ * C_; K = C_; k0 = blockIdx.y * 32;
        oh = ooh; ol = ool; obase = (size_t)layer * C_ * C_;
    } else {
        in = w2 + (size_t)layer * F_ * C_; K = F_; k0 = (blockIdx.y - 32) * 32;
        oh = o2h; ol = o2l; obase = (size_t)layer * F_ * C_;
    }
    const int n0 = blockIdx.x * 32;
    #pragma unroll
    for (int j = 0; j < 4; j++) {
        int k = k0 + threadIdx.y + j * 8;
        t[threadIdx.y + j * 8][threadIdx.x] = in[(size_t)k * C_ + n0 + threadIdx.x];
    }
    __syncthreads();
    #pragma unroll
    for (int j = 0; j < 4; j++) {
        int n = n0 + threadIdx.y + j * 8;
        float v = t[threadIdx.x][threadIdx.y + j * 8];
        __nv_bfloat16 h, l;
        split1(v, h, l);
        size_t off = obase + (size_t)n * K + k0 + threadIdx.x;
        oh[off] = h;
        ol[off] = l;
    }
}

// ===========================================================================
// LayerNorm
// ===========================================================================
__global__ void layernorm_bf16_kernel(const float* __restrict__ x,
                                      const float* __restrict__ g,
                                      const float* __restrict__ b,
                                      __nv_bfloat16* __restrict__ yh,
                                      __nv_bfloat16* __restrict__ yl) {
    int row = blockIdx.x;
    int tid = threadIdx.x;
    int c = tid * 4;

    float4 xv = *(const float4*)(x + (size_t)row * C_ + c);
    float s  = xv.x + xv.y + xv.z + xv.w;
    float sq = xv.x*xv.x + xv.y*xv.y + xv.z*xv.z + xv.w*xv.w;

    __shared__ float ssum[256];
    __shared__ float ssq[256];
    ssum[tid] = s; ssq[tid] = sq;
    __syncthreads();
    #pragma unroll
    for (int st = 128; st > 0; st >>= 1) {
        if (tid < st) { ssum[tid] += ssum[tid+st]; ssq[tid] += ssq[tid+st]; }
        __syncthreads();
    }
    __shared__ float s_mean, s_rstd;
    if (tid == 0) {
        float mean = ssum[0] * (1.0f / C_);
        float var  = ssq[0] * (1.0f / C_) - mean * mean;
        s_mean = mean;
        s_rstd = rsqrtf(var + 1e-5f);
    }
    __syncthreads();
    float mean = s_mean, rstd = s_rstd;

    float4 gv = *(const float4*)(g + c);
    float4 bv = *(const float4*)(b + c);
    float4 o;
    o.x = (xv.x - mean) * rstd * gv.x + bv.x;
    o.y = (xv.y - mean) * rstd * gv.y + bv.y;
    o.z = (xv.z - mean) * rstd * gv.z + bv.z;
    o.w = (xv.w - mean) * rstd * gv.w + bv.w;
    split4_store(o, yh + (size_t)row * C_ + c, yl + (size_t)row * C_ + c);
}

__global__ void layernorm_last_kernel(const float* __restrict__ x,
                                      const float* __restrict__ g,
                                      const float* __restrict__ b,
                                      float* __restrict__ y) {
    int row_in  = blockIdx.x * T_ + (T_ - 1);
    int tid = threadIdx.x;
    int c = tid * 4;

    float4 xv = *(const float4*)(x + (size_t)row_in * C_ + c);
    float s  = xv.x + xv.y + xv.z + xv.w;
    float sq = xv.x*xv.x + xv.y*xv.y + xv.z*xv.z + xv.w*xv.w;

    __shared__ float ssum[256];
    __shared__ float ssq[256];
    ssum[tid] = s; ssq[tid] = sq;
    __syncthreads();
    #pragma unroll
    for (int st = 128; st > 0; st >>= 1) {
        if (tid < st) { ssum[tid] += ssum[tid+st]; ssq[tid] += ssq[tid+st]; }
        __syncthreads();
    }
    __shared__ float s_mean, s_rstd;
    if (tid == 0) {
        float mean = ssum[0] * (1.0f / C_);
        float var  = ssq[0] * (1.0f / C_) - mean * mean;
        s_mean = mean;
        s_rstd = rsqrtf(var + 1e-5f);
    }
    __syncthreads();
    float mean = s_mean, rstd = s_rstd;

    float4 gv = *(const float4*)(g + c);
    float4 bv = *(const float4*)(b + c);
    float4 o;
    o.x = (xv.x - mean) * rstd * gv.x + bv.x;
    o.y = (xv.y - mean) * rstd * gv.y + bv.y;
    o.z = (xv.z - mean) * rstd * gv.z + bv.z;
    o.w = (xv.w - mean) * rstd * gv.w + bv.w;
    *(float4*)(y + (size_t)blockIdx.x * C_ + c) = o;
}

// ===========================================================================
// mma.sync split-bf16 GEMM (256 threads, BM template, MI=BM/32).
// VFUSE: columns n >= 2048 written transposed+split into vth/vtl.
// ===========================================================================
#define SWZ(row, chunk) ((((chunk) ^ ((row) & 7)) << 4) + (row) * 128)
#define GEMM_SMEM 196608

template<int ROWS>
__device__ __forceinline__ void load_tile_cp(const __nv_bfloat16* __restrict__ src,
                                             int row0, int K, int kt,
                                             uint32_t sbase, int tid) {
    #pragma unroll
    for (int r = 0; r < ROWS / 32; r++) {
        int cid = tid + r * 256;
        int row = cid >> 3;
        int c   = cid & 7;
        const __nv_bfloat16* g = src + (size_t)(row0 + row) * K + kt * 64 + c * 8;
        CP_ASYNC16(sbase + SWZ(row, c), g);
    }
}

template<int BM, bool RELU, bool RES, bool OUTBF16, bool VFUSE>
__global__ __launch_bounds__(256, 1)
void gemm_tc(const __nv_bfloat16* __restrict__ Ah, const __nv_bfloat16* __restrict__ Al,
             const __nv_bfloat16* __restrict__ Bh, const __nv_bfloat16* __restrict__ Bl,
             const float* __restrict__ bias, const float* __restrict__ res,
             float* __restrict__ Cf,
             __nv_bfloat16* __restrict__ Ch, __nv_bfloat16* __restrict__ Cl,
             __nv_bfloat16* __restrict__ vth, __nv_bfloat16* __restrict__ vtl,
             int M, int N, int K) {
    constexpr int MI      = BM / 32;
    constexpr int A_TILE  = BM * 128;
    constexpr int B_TILE  = 16384;
    constexpr int STG     = (BM == 128) ? 3 : 2;
    constexpr int STAGE   = 2 * A_TILE + 2 * B_TILE;

    extern __shared__ char dsm[];
    const uint32_t base = smem_u32(dsm);

    const int tid  = threadIdx.x;
    const int wid  = tid >> 5;
    const int lane = tid & 31;
    const int m0 = blockIdx.y * BM;
    const int n0 = blockIdx.x * 128;
    const int wm = wid & 1;
    const int wn = wid >> 1;

    float acc[MI][4][4];
    #pragma unroll
    for (int i = 0; i < MI; i++)
        #pragma unroll
        for (int j = 0; j < 4; j++)
            #pragma unroll
            for (int r = 0; r < 4; r++) acc[i][j][r] = 0.0f;

    const int nkt = K >> 6;

    const int a_row  = wm * (BM / 2) + (lane & 15);
    const int a_csel = lane >> 4;
    const int b_row  = wn * 32 + ((lane & 7) | ((lane & 16) >> 1));
    const int b_csel = (lane >> 3) & 1;

    {
        load_tile_cp<BM>(Ah, m0, K, 0, base, tid);
        load_tile_cp<BM>(Al, m0, K, 0, base + A_TILE, tid);
        load_tile_cp<128>(Bh, n0, K, 0, base + 2 * A_TILE, tid);
        load_tile_cp<128>(Bl, n0, K, 0, base + 2 * A_TILE + B_TILE, tid);
        CP_COMMIT();
        load_tile_cp<BM>(Ah, m0, K, 1, base + STAGE, tid);
        load_tile_cp<BM>(Al, m0, K, 1, base + STAGE + A_TILE, tid);
        load_tile_cp<128>(Bh, n0, K, 1, base + STAGE + 2 * A_TILE, tid);
        load_tile_cp<128>(Bl, n0, K, 1, base + STAGE + 2 * A_TILE + B_TILE, tid);
        CP_COMMIT();
    }

    for (int kt = 0; kt < nkt; kt++) {
        if (kt + 1 < nkt) { CP_WAIT1(); } else { CP_WAIT0(); }
        __syncthreads();

        if (STG == 3 && kt + 2 < nkt) {
            const uint32_t nb = base + ((kt + 2) % 3) * STAGE;
            load_tile_cp<BM>(Ah, m0, K, kt + 2, nb, tid);
            load_tile_cp<BM>(Al, m0, K, kt + 2, nb + A_TILE, tid);
            load_tile_cp<128>(Bh, n0, K, kt + 2, nb + 2 * A_TILE, tid);
            load_tile_cp<128>(Bl, n0, K, kt + 2, nb + 2 * A_TILE + B_TILE, tid);
            CP_COMMIT();
        }

        const uint32_t sb  = base + (kt % STG) * STAGE;
        const uint32_t sAh = sb;
        const uint32_t sAl = sb + A_TILE;
        const uint32_t sBh = sb + 2 * A_TILE;
        const uint32_t sBl = sb + 2 * A_TILE + B_TILE;

        #pragma unroll
        for (int ks = 0; ks < 4; ks++) {
            const int ac = ks * 2 + a_csel;
            const int bc = ks * 2 + b_csel;
            uint32_t bh[4][2], bl[4][2];
            #pragma unroll
            for (int nj = 0; nj < 2; nj++) {
                int row = b_row + nj * 16;
                ldm_x4(sBh + SWZ(row, bc), bh[nj*2][0], bh[nj*2][1], bh[nj*2+1][0], bh[nj*2+1][1]);
                ldm_x4(sBl + SWZ(row, bc), bl[nj*2][0], bl[nj*2][1], bl[nj*2+1][0], bl[nj*2+1][1]);
            }
            #pragma unroll
            for (int mi = 0; mi < MI; mi++) {
                uint32_t ah0, ah1, ah2, ah3, al0, al1, al2, al3;
                int row = a_row + mi * 16;
                ldm_x4(sAh + SWZ(row, ac), ah0, ah1, ah2, ah3);
                ldm_x4(sAl + SWZ(row, ac), al0, al1, al2, al3);
                #pragma unroll
                for (int ni = 0; ni < 4; ni++) {
                    mma_bf16(acc[mi][ni][0], acc[mi][ni][1], acc[mi][ni][2], acc[mi][ni][3],
                             ah0, ah1, ah2, ah3, bh[ni][0], bh[ni][1]);
                    mma_bf16(acc[mi][ni][0], acc[mi][ni][1], acc[mi][ni][2], acc[mi][ni][3],
                             ah0, ah1, ah2, ah3, bl[ni][0], bl[ni][1]);
                    mma_bf16(acc[mi][ni][0], acc[mi][ni][1], acc[mi][ni][2], acc[mi][ni][3],
                             al0, al1, al2, al3, bh[ni][0], bh[ni][1]);
                }
            }
        }

        if (STG == 2) {
            __syncthreads();
            if (kt + 2 < nkt) {
                const uint32_t nb = base + (kt & 1) * STAGE;
                load_tile_cp<BM>(Ah, m0, K, kt + 2, nb, tid);
                load_tile_cp<BM>(Al, m0, K, kt + 2, nb + A_TILE, tid);
                load_tile_cp<128>(Bh, n0, K, kt + 2, nb + 2 * A_TILE, tid);
                load_tile_cp<128>(Bl, n0, K, kt + 2, nb + 2 * A_TILE + B_TILE, tid);
                CP_COMMIT();
            }
        }
    }

    const int qm = lane >> 2;
    const int qn = (lane & 3) * 2;
    const bool vblock = VFUSE && (n0 >= 2 * C_);
    #pragma unroll
    for (int mi = 0; mi < MI; mi++) {
        #pragma unroll
        for (int ni = 0; ni < 4; ni++) {
            const int n = n0 + wn * 32 + ni * 8 + qn;
            float2 bv = *(const float2*)(bias + n);
            #pragma unroll
            for (int half = 0; half < 2; half++) {
                const int m = m0 + wm * (BM / 2) + mi * 16 + qm + half * 8;
                float vx = acc[mi][ni][half*2 + 0] + bv.x;
                float vy = acc[mi][ni][half*2 + 1] + bv.y;
                if (RELU) { vx = fmaxf(vx, 0.f); vy = fmaxf(vy, 0.f); }
                if (RES) {
                    float2 rv = *(const float2*)(res + (size_t)m * N + n);
                    vx += rv.x; vy += rv.y;
                }
                if (vblock) {
                    const int t  = m & (T_ - 1);
                    const int bb = m >> 11;
                    const int nv = n - 2 * C_;
                    const int hh = nv >> 6;
                    const int d  = nv & 63;
                    __nv_bfloat16 h0, l0, h1, l1;
                    split1(vx, h0, l0);
                    split1(vy, h1, l1);
                    size_t vo = ((size_t)(bb * H_ + hh) * 64 + d) * T_ + t;
                    vth[vo]      = h0;
                    vth[vo + T_] = h1;
                    vtl[vo]      = l0;
                    vtl[vo + T_] = l1;
                } else if (OUTBF16) {
                    split2_store(vx, vy, Ch + (size_t)m * N + n, Cl + (size_t)m * N + n);
                } else {
                    *(float2*)(Cf + (size_t)m * N + n) = make_float2(vx, vy);
                }
            }
        }
    }
}

// ===========================================================================
// Tensor-core flash attention (64 queries/CTA, 4 warps).
// Softmax in base-2 domain: scores scaled by 0.125*log2(e), exp2f throughout.
// ===========================================================================
#define ATT_SMEM (16384 + 32768)
#define SCALE_LOG2E 0.18033688f   // 0.125 * log2(e)

__global__ __launch_bounds__(128)
void attention_mma_kernel(const __nv_bfloat16* __restrict__ qkvh,
                          const __nv_bfloat16* __restrict__ qkvl,
                          const __nv_bfloat16* __restrict__ Vth,
                          const __nv_bfloat16* __restrict__ Vtl,
                          __nv_bfloat16* __restrict__ aoh,
                          __nv_bfloat16* __restrict__ aol) {
    extern __shared__ char dsm[];
    const uint32_t base = smem_u32(dsm);
    const uint32_t sQh = base;
    const uint32_t sQl = base + 8192;
    const uint32_t sKh = base + 16384;
    const uint32_t sKl = base + 24576;
    const uint32_t sVh = base + 32768;
    const uint32_t sVl = base + 40960;

    const int b  = blockIdx.z;
    const int h  = blockIdx.y;
    const int qt = (T_ / 64 - 1) - blockIdx.x;
    const int tid  = threadIdx.x;
    const int wid  = tid >> 5;
    const int lane = tid & 31;
    const int m_base = wid * 16;

    #pragma unroll
    for (int r = 0; r < 4; r++) {
        int cid = tid + r * 128;
        int row = cid >> 3;
        int c   = cid & 7;
        size_t goff = (size_t)(b * T_ + qt * 64 + row) * QKV_ + h * 64 + c * 8;
        CP_ASYNC16(sQh + SWZ(row, c), qkvh + goff);
        CP_ASYNC16(sQl + SWZ(row, c), qkvl + goff);
    }
    CP_COMMIT(); CP_WAIT0();
    __syncthreads();

    const int a_row  = m_base + (lane & 15);
    const int a_csel = lane >> 4;
    uint32_t qfh[4][4], qfl[4][4];
    #pragma unroll
    for (int ks = 0; ks < 4; ks++) {
        ldm_x4(sQh + SWZ(a_row, ks*2 + a_csel), qfh[ks][0], qfh[ks][1], qfh[ks][2], qfh[ks][3]);
        ldm_x4(sQl + SWZ(a_row, ks*2 + a_csel), qfl[ks][0], qfl[ks][1], qfl[ks][2], qfl[ks][3]);
    }

    const int b_row_l = (lane & 7) | ((lane & 16) >> 1);
    const int b_csel  = (lane >> 3) & 1;
    const int qm = lane >> 2;
    const int qn = (lane & 3) * 2;

    float o[8][4];
    #pragma unroll
    for (int n = 0; n < 8; n++)
        #pragma unroll
        for (int r = 0; r < 4; r++) o[n][r] = 0.0f;
    float mrow[2] = {-FLT_MAX, -FLT_MAX};
    float lrow[2] = {0.0f, 0.0f};

    for (int kt = 0; kt <= qt; kt++) {
        __syncthreads();
        #pragma unroll
        for (int r = 0; r < 4; r++) {
            int cid = tid + r * 128;
            int row = cid >> 3;
            int c   = cid & 7;
            size_t koff = (size_t)(b * T_ + kt * 64 + row) * QKV_ + C_ + h * 64 + c * 8;
            size_t voff = ((size_t)(b * H_ + h) * 64 + row) * T_ + kt * 64 + c * 8;
            CP_ASYNC16(sKh + SWZ(row, c), qkvh + koff);
            CP_ASYNC16(sKl + SWZ(row, c), qkvl + koff);
            CP_ASYNC16(sVh + SWZ(row, c), Vth + voff);
            CP_ASYNC16(sVl + SWZ(row, c), Vtl + voff);
        }
        CP_COMMIT(); CP_WAIT0();
        __syncthreads();

        float sc[8][4];
        #pragma unroll
        for (int n = 0; n < 8; n++)
            #pragma unroll
            for (int r = 0; r < 4; r++) sc[n][r] = 0.0f;

        #pragma unroll
        for (int ks = 0; ks < 4; ks++) {
            const int bc = ks * 2 + b_csel;
            #pragma unroll
            for (int g = 0; g < 4; g++) {
                uint32_t r0, r1, r2, r3, s0, s1, s2, s3;
                ldm_x4(sKh + SWZ(g * 16 + b_row_l, bc), r0, r1, r2, r3);
                ldm_x4(sKl + SWZ(g * 16 + b_row_l, bc), s0, s1, s2, s3);
                mma_bf16(sc[2*g][0], sc[2*g][1], sc[2*g][2], sc[2*g][3],
                         qfh[ks][0], qfh[ks][1], qfh[ks][2], qfh[ks][3], r0, r1);
                mma_bf16(sc[2*g+1][0], sc[2*g+1][1], sc[2*g+1][2], sc[2*g+1][3],
                         qfh[ks][0], qfh[ks][1], qfh[ks][2], qfh[ks][3], r2, r3);
                mma_bf16(sc[2*g][0], sc[2*g][1], sc[2*g][2], sc[2*g][3],
                         qfh[ks][0], qfh[ks][1], qfh[ks][2], qfh[ks][3], s0, s1);
                mma_bf16(sc[2*g+1][0], sc[2*g+1][1], sc[2*g+1][2], sc[2*g+1][3],
                         qfh[ks][0], qfh[ks][1], qfh[ks][2], qfh[ks][3], s2, s3);
                mma_bf16(sc[2*g][0], sc[2*g][1], sc[2*g][2], sc[2*g][3],
                         qfl[ks][0], qfl[ks][1], qfl[ks][2], qfl[ks][3], r0, r1);
                mma_bf16(sc[2*g+1][0], sc[2*g+1][1], sc[2*g+1][2], sc[2*g+1][3],
                         qfl[ks][0], qfl[ks][1], qfl[ks][2], qfl[ks][3], r2, r3);
            }
        }

        // scale into base-2 softmax domain (0.125 * log2 e)
        #pragma unroll
        for (int n = 0; n < 8; n++)
            #pragma unroll
            for (int r = 0; r < 4; r++) sc[n][r] *= SCALE_LOG2E;

        if (kt == qt) {
            const int row0 = m_base + qm;
            const int row1 = row0 + 8;
            #pragma unroll
            for (int n = 0; n < 8; n++) {
                int col = n * 8 + qn;
                if (col     > row0) sc[n][0] = -FLT_MAX;
                if (col + 1 > row0) sc[n][1] = -FLT_MAX;
                if (col     > row1) sc[n][2] = -FLT_MAX;
                if (col + 1 > row1) sc[n][3] = -FLT_MAX;
            }
        }

        #pragma unroll
        for (int r = 0; r < 2; r++) {
            float mx = -FLT_MAX;
            #pragma unroll
            for (int n = 0; n < 8; n++) {
                mx = fmaxf(mx, sc[n][2*r]);
                mx = fmaxf(mx, sc[n][2*r + 1]);
            }
            mx = fmaxf(mx, __shfl_xor_sync(0xffffffffu, mx, 1));
            mx = fmaxf(mx, __shfl_xor_sync(0xffffffffu, mx, 2));
            float mnew = fmaxf(mrow[r], mx);
            float alpha = exp2f(mrow[r] - mnew);
            float sum = 0.0f;
            #pragma unroll
            for (int n = 0; n < 8; n++) {
                float p0 = exp2f(sc[n][2*r]     - mnew);
                float p1 = exp2f(sc[n][2*r + 1] - mnew);
                sc[n][2*r]     = p0;
                sc[n][2*r + 1] = p1;
                sum += p0 + p1;
            }
            sum += __shfl_xor_sync(0xffffffffu, sum, 1);
            sum += __shfl_xor_sync(0xffffffffu, sum, 2);
            lrow[r] = lrow[r] * alpha + sum;
            mrow[r] = mnew;
            #pragma unroll
            for (int n = 0; n < 8; n++) {
                o[n][2*r]     *= alpha;
                o[n][2*r + 1] *= alpha;
            }
        }

        #pragma unroll
        for (int ks = 0; ks < 4; ks++) {
            uint32_t ph0, ph1, ph2, ph3, pl0, pl1, pl2, pl3;
            pack_split(sc[2*ks][0],   sc[2*ks][1],   ph0, pl0);
            pack_split(sc[2*ks][2],   sc[2*ks][3],   ph1, pl1);
            pack_split(sc[2*ks+1][0], sc[2*ks+1][1], ph2, pl2);
            pack_split(sc[2*ks+1][2], sc[2*ks+1][3], ph3, pl3);
            const int bc = ks * 2 + b_csel;
            #pragma unroll
            for (int g = 0; g < 4; g++) {
                uint32_t r0, r1, r2, r3, s0, s1, s2, s3;
                ldm_x4(sVh + SWZ(g * 16 + b_row_l, bc), r0, r1, r2, r3);
                ldm_x4(sVl + SWZ(g * 16 + b_row_l, bc), s0, s1, s2, s3);
                mma_bf16(o[2*g][0], o[2*g][1], o[2*g][2], o[2*g][3],
                         ph0, ph1, ph2, ph3, r0, r1);
                mma_bf16(o[2*g+1][0], o[2*g+1][1], o[2*g+1][2], o[2*g+1][3],
                         ph0, ph1, ph2, ph3, r2, r3);
                mma_bf16(o[2*g][0], o[2*g][1], o[2*g][2], o[2*g][3],
                         ph0, ph1, ph2, ph3, s0, s1);
                mma_bf16(o[2*g+1][0], o[2*g+1][1], o[2*g+1][2], o[2*g+1][3],
                         ph0, ph1, ph2, ph3, s2, s3);
                mma_bf16(o[2*g][0], o[2*g][1], o[2*g][2], o[2*g][3],
                         pl0, pl1, pl2, pl3, r0, r1);
                mma_bf16(o[2*g+1][0], o[2*g+1][1], o[2*g+1][2], o[2*g+1][3],
                         pl0, pl1, pl2, pl3, r2, r3);
            }
        }
    }

    const float inv0 = 1.0f / lrow[0];
    const float inv1 = 1.0f / lrow[1];
    const size_t row0 = (size_t)(b * T_ + qt * 64 + m_base + qm) * C_;
    const size_t row1 = row0 + 8 * C_;
    #pragma unroll
    for (int n = 0; n < 8; n++) {
        int col = h * 64 + n * 8 + qn;
        split2_store(o[n][0] * inv0, o[n][1] * inv0, aoh + row0 + col, aol + row0 + col);
        split2_store(o[n][2] * inv1, o[n][3] * inv1, aoh + row1 + col, aol + row1 + col);
    }
}

// ===========================================================================
// Logits (per-batch blocks, R8 version)
// ===========================================================================
__global__ void logits_kernel(const float* __restrict__ xf,
                              const float* __restrict__ W,
                              const float* __restrict__ bias,
                              float* __restrict__ out) {
    __shared__ float xs[C_];
    const int b = blockIdx.y;
    const int tid = threadIdx.x;
    #pragma unroll
    for (int r = 0; r < C_ / 128; r++)
        xs[tid + r * 128] = xf[b * C_ + tid + r * 128];
    __syncthreads();

    int vcol = blockIdx.x * 128 + tid;
    float acc = bias[vcol];
    const float* wp = W + vcol;
    #pragma unroll 8
    for (int k = 0; k < C_; k++)
        acc = fmaf(xs[k], wp[(size_t)k * V_], acc);
    out[(size_t)b * V_ + vcol] = acc;
}

// ===========================================================================
// Launch (R8 structure exactly)
// ===========================================================================
extern "C" void kernel_launch(void* const* d_in, const int* in_sizes, int n_in,
                              void* d_out, int out_size) {
    const int*   idx   = (const int*)  d_in[0];
    const float* emb   = (const float*)d_in[1];
    const float* pos   = (const float*)d_in[2];
    const float* ln1_g = (const float*)d_in[3];
    const float* ln1_b = (const float*)d_in[4];
    const float* wq    = (const float*)d_in[5];
    const float* bq    = (const float*)d_in[6];
    const float* wk    = (const float*)d_in[7];
    const float* bk    = (const float*)d_in[8];
    const float* wv    = (const float*)d_in[9];
    const float* bv    = (const float*)d_in[10];
    const float* wo    = (const float*)d_in[11];
    const float* bo    = (const float*)d_in[12];
    const float* ln2_g = (const float*)d_in[13];
    const float* ln2_b = (const float*)d_in[14];
    const float* w1    = (const float*)d_in[15];
    const float* b1    = (const float*)d_in[16];
    const float* w2    = (const float*)d_in[17];
    const float* b2    = (const float*)d_in[18];
    const float* lnf_g = (const float*)d_in[19];
    const float* lnf_b = (const float*)d_in[20];
    const float* out_w = (const float*)d_in[21];
    const float* out_b = (const float*)d_in[22];
    float* out = (float*)d_out;

    float *x, *xf, *bqkv;
    cudaGetSymbolAddress((void**)&x,    g_x);
    cudaGetSymbolAddress((void**)&xf,   g_xf);
    cudaGetSymbolAddress((void**)&bqkv, g_bqkv);

    __nv_bfloat16 *h_h, *h_l, *qkvh, *qkvl, *vth, *vtl, *ao_h, *ao_l, *hid_h, *hid_l;
    cudaGetSymbolAddress((void**)&h_h,   g_h_h);
    cudaGetSymbolAddress((void**)&h_l,   g_h_l);
    cudaGetSymbolAddress((void**)&qkvh,  g_qkvh);
    cudaGetSymbolAddress((void**)&qkvl,  g_qkvl);
    cudaGetSymbolAddress((void**)&vth,   g_vth);
    cudaGetSymbolAddress((void**)&vtl,   g_vtl);
    cudaGetSymbolAddress((void**)&ao_h,  g_ao_h);
    cudaGetSymbolAddress((void**)&ao_l,  g_ao_l);
    cudaGetSymbolAddress((void**)&hid_h, g_hid_h);
    cudaGetSymbolAddress((void**)&hid_l, g_hid_l);

    __nv_bfloat16 *wqkvT_h, *wqkvT_l, *woT_h, *woT_l, *w1T_h, *w1T_l, *w2T_h, *w2T_l;
    cudaGetSymbolAddress((void**)&wqkvT_h, g_wqkvT_h);
    cudaGetSymbolAddress((void**)&wqkvT_l, g_wqkvT_l);
    cudaGetSymbolAddress((void**)&woT_h, g_woT_h);
    cudaGetSymbolAddress((void**)&woT_l, g_woT_l);
    cudaGetSymbolAddress((void**)&w1T_h, g_w1T_h);
    cudaGetSymbolAddress((void**)&w1T_l, g_w1T_l);
    cudaGetSymbolAddress((void**)&w2T_h, g_w2T_h);
    cudaGetSymbolAddress((void**)&w2T_l, g_w2T_l);

    cudaFuncSetAttribute(gemm_tc<256, false, false, true, true>,
                         cudaFuncAttributeMaxDynamicSharedMemorySize, GEMM_SMEM);
    cudaFuncSetAttribute(gemm_tc<128, true, false, true, false>,
                         cudaFuncAttributeMaxDynamicSharedMemorySize, GEMM_SMEM);
    cudaFuncSetAttribute(gemm_tc<256, false, true, false, false>,
                         cudaFuncAttributeMaxDynamicSharedMemorySize, GEMM_SMEM);
    cudaFuncSetAttribute(attention_mma_kernel,
                         cudaFuncAttributeMaxDynamicSharedMemorySize, ATT_SMEM);

    // Weight prep: 3 launches
    {
        dim3 blk(32, 8);
        transpose_split_qkv_kernel<<<dim3(32, 32, 24), blk>>>(wq, wk, wv, wqkvT_h, wqkvT_l);
        transpose_split_wo_w2_kernel<<<dim3(32, 160, 8), blk>>>(wo, w2, woT_h, woT_l, w2T_h, w2T_l);
        transpose_split_kernel<<<dim3(128, 32, 8), blk>>>(w1, w1T_h, w1T_l, C_, F_, (size_t)C_ * F_);
    }

    embed_kernel<<<BT_, 256>>>(idx, emb, pos, bq, bk, bv, x, bqkv);

    dim3 gemm_qkv(QKV_ / 128, BT_ / 256);  // (24, 16)  BM=256, V fused-transposed
    dim3 gemm_cc(C_ / 128, BT_ / 256);     // (8, 16)   BM=256
    dim3 gemm_cf(F_ / 128, BT_ / 128);     // (32, 32)  BM=128
    dim3 attn_grid(T_ / 64, H_, B_);

    for (int l = 0; l < L_; l++) {
        layernorm_bf16_kernel<<<BT_, 256>>>(x, ln1_g + l * C_, ln1_b + l * C_, h_h, h_l);

        // merged QKV projection; V columns written straight into vt layout
        gemm_tc<256, false, false, true, true><<<gemm_qkv, 256, GEMM_SMEM>>>(
            h_h, h_l, wqkvT_h + (size_t)l * QKV_ * C_, wqkvT_l + (size_t)l * QKV_ * C_,
            bqkv + l * QKV_, nullptr, nullptr, qkvh, qkvl, vth, vtl, BT_, QKV_, C_);

        attention_mma_kernel<<<attn_grid, 128, ATT_SMEM>>>(
            qkvh, qkvl, vth, vtl, ao_h, ao_l);

        // x = x + (ao @ wo + bo)
        gemm_tc<256, false, true, false, false><<<gemm_cc, 256, GEMM_SMEM>>>(
            ao_h, ao_l, woT_h + (size_t)l * C_ * C_, woT_l + (size_t)l * C_ * C_,
            bo + l * C_, x, x, nullptr, nullptr, nullptr, nullptr, BT_, C_, C_);

        layernorm_bf16_kernel<<<BT_, 256>>>(x, ln2_g + l * C_, ln2_b + l * C_, h_h, h_l);

        // hid = relu(h @ w1 + b1)
        gemm_tc<128, true, false, true, false><<<gemm_cf, 256, GEMM_SMEM>>>(
            h_h, h_l, w1T_h + (size_t)l * C_ * F_, w1T_l + (size_t)l * C_ * F_,
            b1 + l * F_, nullptr, nullptr, hid_h, hid_l, nullptr, nullptr, BT_, F_, C_);
        // x = x + (hid @ w2 + b2)
        gemm_tc<256, false, true, false, false><<<gemm_cc, 256, GEMM_SMEM>>>(
            hid_h, hid_l, w2T_h + (size_t)l * F_ * C_, w2T_l + (size_t)l * F_ * C_,
            b2 + l * C_, x, x, nullptr, nullptr, nullptr, nullptr, BT_, C_, F_);
    }

    layernorm_last_kernel<<<B_, 256>>>(x, lnf_g, lnf_b, xf);
    logits_kernel<<<dim3(V_ / 128, B_), 128>>>(xf, out_w, out_b, out);
}

// round 17
// speedup vs baseline: 1.0375x; 1.0083x over previous
#include <cuda_runtime.h>
#include <cuda_bf16.h>
#include <float.h>
#include <cstdint>

// Problem constants
#define V_   32000
#define C_   1024
#define H_   16
#define L_   8
#define F_   4096
#define B_   2
#define T_   2048
#define D_   64
#define BT_  (B_*T_)
#define QKV_ (3*C_)

// ===========================================================================
// helpers
// ===========================================================================
__device__ __forceinline__ uint32_t smem_u32(const void* p) {
    uint32_t a;
    asm("{ .reg .u64 t; cvta.to.shared.u64 t, %1; cvt.u32.u64 %0, t; }"
        : "=r"(a) : "l"(p));
    return a;
}

#define CP_ASYNC16(saddr, gptr) \
    asm volatile("cp.async.cg.shared.global [%0], [%1], 16;" \
                 :: "r"(saddr), "l"(gptr) : "memory")
#define CP_COMMIT() asm volatile("cp.async.commit_group;" ::: "memory")
#define CP_WAIT1()  asm volatile("cp.async.wait_group 1;" ::: "memory")
#define CP_WAIT0()  asm volatile("cp.async.wait_group 0;" ::: "memory")

__device__ __forceinline__ void ldm_x4(uint32_t addr, uint32_t& r0, uint32_t& r1,
                                       uint32_t& r2, uint32_t& r3) {
    asm volatile("ldmatrix.sync.aligned.m8n8.x4.shared.b16 {%0,%1,%2,%3}, [%4];"
                 : "=r"(r0), "=r"(r1), "=r"(r2), "=r"(r3) : "r"(addr));
}

__device__ __forceinline__ void mma_bf16(float& d0, float& d1, float& d2, float& d3,
                                         uint32_t a0, uint32_t a1, uint32_t a2, uint32_t a3,
                                         uint32_t b0, uint32_t b1) {
    asm volatile(
        "mma.sync.aligned.m16n8k16.row.col.f32.bf16.bf16.f32 "
        "{%0,%1,%2,%3}, {%4,%5,%6,%7}, {%8,%9}, {%0,%1,%2,%3};"
        : "+f"(d0), "+f"(d1), "+f"(d2), "+f"(d3)
        : "r"(a0), "r"(a1), "r"(a2), "r"(a3), "r"(b0), "r"(b1));
}

// bf16 hi/lo split helpers
__device__ __forceinline__ void split1(float v, __nv_bfloat16& h, __nv_bfloat16& l) {
    h = __float2bfloat16(v);
    l = __float2bfloat16(v - __bfloat162float(h));
}
__device__ __forceinline__ void split2_store(float x, float y,
                                             __nv_bfloat16* ph, __nv_bfloat16* pl) {
    __nv_bfloat16 h0, h1, l0, l1;
    split1(x, h0, l0); split1(y, h1, l1);
    __nv_bfloat162 H; H.x = h0; H.y = h1;
    __nv_bfloat162 L; L.x = l0; L.y = l1;
    *(__nv_bfloat162*)ph = H;
    *(__nv_bfloat162*)pl = L;
}
__device__ __forceinline__ void split4_store(float4 v, __nv_bfloat16* ph, __nv_bfloat16* pl) {
    split2_store(v.x, v.y, ph, pl);
    split2_store(v.z, v.w, ph + 2, pl + 2);
}
__device__ __forceinline__ void pack_split(float x, float y, uint32_t& hi, uint32_t& lo) {
    __nv_bfloat16 hx, lx, hy, ly;
    split1(x, hx, lx); split1(y, hy, ly);
    __nv_bfloat162 Hh; Hh.x = hx; Hh.y = hy;
    __nv_bfloat162 Ll; Ll.x = lx; Ll.y = ly;
    hi = *reinterpret_cast<uint32_t*>(&Hh);
    lo = *reinterpret_cast<uint32_t*>(&Ll);
}

// ===========================================================================
// Scratch
// ===========================================================================
__device__ float g_x  [BT_ * C_];
__device__ float g_xf [B_ * C_];
__device__ float g_bqkv[L_ * QKV_];

__device__ __nv_bfloat16 g_h_h  [BT_ * C_];
__device__ __nv_bfloat16 g_h_l  [BT_ * C_];
__device__ __nv_bfloat16 g_qkvh [(size_t)BT_ * QKV_];
__device__ __nv_bfloat16 g_qkvl [(size_t)BT_ * QKV_];
__device__ __nv_bfloat16 g_vth  [B_ * H_ * D_ * T_];
__device__ __nv_bfloat16 g_vtl  [B_ * H_ * D_ * T_];
__device__ __nv_bfloat16 g_ao_h [BT_ * C_];
__device__ __nv_bfloat16 g_ao_l [BT_ * C_];
__device__ __nv_bfloat16 g_hid_h[BT_ * F_];
__device__ __nv_bfloat16 g_hid_l[BT_ * F_];

__device__ __nv_bfloat16 g_wqkvT_h[(size_t)L_ * QKV_ * C_];
__device__ __nv_bfloat16 g_wqkvT_l[(size_t)L_ * QKV_ * C_];
__device__ __nv_bfloat16 g_woT_h[L_ * C_ * C_];
__device__ __nv_bfloat16 g_woT_l[L_ * C_ * C_];
__device__ __nv_bfloat16 g_w1T_h[L_ * C_ * F_];
__device__ __nv_bfloat16 g_w1T_l[L_ * C_ * F_];
__device__ __nv_bfloat16 g_w2T_h[L_ * F_ * C_];
__device__ __nv_bfloat16 g_w2T_l[L_ * F_ * C_];

// ===========================================================================
// Embedding (+ QKV bias concat)
// ===========================================================================
__global__ void embed_kernel(const int* __restrict__ idx,
                             const float* __restrict__ emb,
                             const float* __restrict__ pos,
                             const float* __restrict__ bq,
                             const float* __restrict__ bk,
                             const float* __restrict__ bv,
                             float* __restrict__ x,
                             float* __restrict__ bqkv) {
    int row = blockIdx.x;
    int t   = row % T_;
    int tok = idx[row];
    int c   = threadIdx.x * 4;
    float4 e = *(const float4*)(emb + (size_t)tok * C_ + c);
    float4 p = *(const float4*)(pos + (size_t)t   * C_ + c);
    float4 o;
    o.x = e.x + p.x; o.y = e.y + p.y; o.z = e.z + p.z; o.w = e.w + p.w;
    *(float4*)(x + (size_t)row * C_ + c) = o;

    if (blockIdx.x < (L_ * QKV_) / 256) {
        int i = blockIdx.x * 256 + threadIdx.x;
        int layer = i / QKV_;
        int col   = i % QKV_;
        float v;
        if (col < C_)           v = bq[layer * C_ + col];
        else if (col < 2 * C_)  v = bk[layer * C_ + col - C_];
        else                    v = bv[layer * C_ + col - 2 * C_];
        bqkv[i] = v;
    }
}

// ===========================================================================
// Weight transposes + bf16 split — 3 launches.
// ===========================================================================
__global__ void transpose_split_kernel(const float* __restrict__ in,
                                       __nv_bfloat16* __restrict__ oh,
                                       __nv_bfloat16* __restrict__ ol,
                                       int K, int N, size_t out_lstride) {
    __shared__ float t[32][33];
    const float* inl = in + (size_t)blockIdx.z * K * N;
    const size_t obase = (size_t)blockIdx.z * out_lstride;
    const int k0 = blockIdx.y * 32;
    const int n0 = blockIdx.x * 32;
    #pragma unroll
    for (int j = 0; j < 4; j++) {
        int k = k0 + threadIdx.y + j * 8;
        t[threadIdx.y + j * 8][threadIdx.x] = inl[(size_t)k * N + n0 + threadIdx.x];
    }
    __syncthreads();
    #pragma unroll
    for (int j = 0; j < 4; j++) {
        int n = n0 + threadIdx.y + j * 8;
        float v = t[threadIdx.x][threadIdx.y + j * 8];
        __nv_bfloat16 h, l;
        split1(v, h, l);
        size_t off = obase + (size_t)n * K + k0 + threadIdx.x;
        oh[off] = h;
        ol[off] = l;
    }
}

__global__ void transpose_split_qkv_kernel(const float* __restrict__ wq,
                                           const float* __restrict__ wk,
                                           const float* __restrict__ wv,
                                           __nv_bfloat16* __restrict__ oh,
                                           __nv_bfloat16* __restrict__ ol) {
    __shared__ float t[32][33];
    const int z = blockIdx.z;
    const int layer = z & 7;
    const int which = z >> 3;
    const float* in = (which == 0 ? wq : which == 1 ? wk : wv) + (size_t)layer * C_ * C_;
    const size_t obase = (size_t)layer * QKV_ * C_ + (size_t)which * C_ * C_;
    const int k0 = blockIdx.y * 32;
    const int n0 = blockIdx.x * 32;
    #pragma unroll
    for (int j = 0; j < 4; j++) {
        int k = k0 + threadIdx.y + j * 8;
        t[threadIdx.y + j * 8][threadIdx.x] = in[(size_t)k * C_ + n0 + threadIdx.x];
    }
    __syncthreads();
    #pragma unroll
    for (int j = 0; j < 4; j++) {
        int n = n0 + threadIdx.y + j * 8;
        float v = t[threadIdx.x][threadIdx.y + j * 8];
        __nv_bfloat16 h, l;
        split1(v, h, l);
        size_t off = obase + (size_t)n * C_ + k0 + threadIdx.x;
        oh[off] = h;
        ol[off] = l;
    }
}

__global__ void transpose_split_wo_w2_kernel(const float* __restrict__ wo,
                                             const float* __restrict__ w2,
                                             __nv_bfloat16* __restrict__ ooh,
                                             __nv_bfloat16* __restrict__ ool,
                                             __nv_bfloat16* __restrict__ o2h,
                                             __nv_bfloat16* __restrict__ o2l) {
    __shared__ float t[32][33];
    const int layer = blockIdx.z;
    const bool isW2 = (blockIdx.y >= 32);
    const float* in;
    __nv_bfloat16 *oh, *ol;
    int K, k0;
    size_t obase;
    if (!isW2) {
        in = wo + (size_t)layer * C_ * C_; K = C_; k0 = blockIdx.y * 32;
        oh = ooh; ol = ool; obase = (size_t)layer * C_ * C_;
    } else {
        in = w2 + (size_t)layer * F_ * C_; K = F_; k0 = (blockIdx.y - 32) * 32;
        oh = o2h; ol = o2l; obase = (size_t)layer * F_ * C_;
    }
    const int n0 = blockIdx.x * 32;
    #pragma unroll
    for (int j = 0; j < 4; j++) {
        int k = k0 + threadIdx.y + j * 8;
        t[threadIdx.y + j * 8][threadIdx.x] = in[(size_t)k * C_ + n0 + threadIdx.x];
    }
    __syncthreads();
    #pragma unroll
    for (int j = 0; j < 4; j++) {
        int n = n0 + threadIdx.y + j * 8;
        float v = t[threadIdx.x][threadIdx.y + j * 8];
        __nv_bfloat16 h, l;
        split1(v, h, l);
        size_t off = obase + (size_t)n * K + k0 + threadIdx.x;
        oh[off] = h;
        ol[off] = l;
    }
}

// ===========================================================================
// LayerNorm — warp-shuffle reduction, single __syncthreads.
// ===========================================================================
__device__ __forceinline__ void ln_reduce(float s, float sq, int tid,
                                          float& mean, float& rstd) {
    #pragma unroll
    for (int off = 16; off; off >>= 1) {
        s  += __shfl_xor_sync(0xffffffffu, s,  off);
        sq += __shfl_xor_sync(0xffffffffu, sq, off);
    }
    __shared__ float ws[8], wqs[8];
    const int wid  = tid >> 5;
    const int lane = tid & 31;
    if (lane == 0) { ws[wid] = s; wqs[wid] = sq; }
    __syncthreads();
    float ts = 0.0f, tq = 0.0f;
    #pragma unroll
    for (int i = 0; i < 8; i++) { ts += ws[i]; tq += wqs[i]; }
    mean = ts * (1.0f / C_);
    float var = tq * (1.0f / C_) - mean * mean;
    rstd = rsqrtf(var + 1e-5f);
}

__global__ void layernorm_bf16_kernel(const float* __restrict__ x,
                                      const float* __restrict__ g,
                                      const float* __restrict__ b,
                                      __nv_bfloat16* __restrict__ yh,
                                      __nv_bfloat16* __restrict__ yl) {
    int row = blockIdx.x;
    int tid = threadIdx.x;
    int c = tid * 4;

    float4 xv = *(const float4*)(x + (size_t)row * C_ + c);
    float s  = xv.x + xv.y + xv.z + xv.w;
    float sq = xv.x*xv.x + xv.y*xv.y + xv.z*xv.z + xv.w*xv.w;

    float mean, rstd;
    ln_reduce(s, sq, tid, mean, rstd);

    float4 gv = *(const float4*)(g + c);
    float4 bv = *(const float4*)(b + c);
    float4 o;
    o.x = (xv.x - mean) * rstd * gv.x + bv.x;
    o.y = (xv.y - mean) * rstd * gv.y + bv.y;
    o.z = (xv.z - mean) * rstd * gv.z + bv.z;
    o.w = (xv.w - mean) * rstd * gv.w + bv.w;
    split4_store(o, yh + (size_t)row * C_ + c, yl + (size_t)row * C_ + c);
}

__global__ void layernorm_last_kernel(const float* __restrict__ x,
                                      const float* __restrict__ g,
                                      const float* __restrict__ b,
                                      float* __restrict__ y) {
    int row_in  = blockIdx.x * T_ + (T_ - 1);
    int tid = threadIdx.x;
    int c = tid * 4;

    float4 xv = *(const float4*)(x + (size_t)row_in * C_ + c);
    float s  = xv.x + xv.y + xv.z + xv.w;
    float sq = xv.x*xv.x + xv.y*xv.y + xv.z*xv.z + xv.w*xv.w;

    float mean, rstd;
    ln_reduce(s, sq, tid, mean, rstd);

    float4 gv = *(const float4*)(g + c);
    float4 bv = *(const float4*)(b + c);
    float4 o;
    o.x = (xv.x - mean) * rstd * gv.x + bv.x;
    o.y = (xv.y - mean) * rstd * gv.y + bv.y;
    o.z = (xv.z - mean) * rstd * gv.z + bv.z;
    o.w = (xv.w - mean) * rstd * gv.w + bv.w;
    *(float4*)(y + (size_t)blockIdx.x * C_ + c) = o;
}

// ===========================================================================
// mma.sync split-bf16 GEMM (256 threads, BM template, MI=BM/32).
// VFUSE: columns n >= 2048 written transposed+split into vth/vtl.
// ===========================================================================
#define SWZ(row, chunk) ((((chunk) ^ ((row) & 7)) << 4) + (row) * 128)
#define GEMM_SMEM 196608

template<int ROWS>
__device__ __forceinline__ void load_tile_cp(const __nv_bfloat16* __restrict__ src,
                                             int row0, int K, int kt,
                                             uint32_t sbase, int tid) {
    #pragma unroll
    for (int r = 0; r < ROWS / 32; r++) {
        int cid = tid + r * 256;
        int row = cid >> 3;
        int c   = cid & 7;
        const __nv_bfloat16* g = src + (size_t)(row0 + row) * K + kt * 64 + c * 8;
        CP_ASYNC16(sbase + SWZ(row, c), g);
    }
}

template<int BM, bool RELU, bool RES, bool OUTBF16, bool VFUSE>
__global__ __launch_bounds__(256, 1)
void gemm_tc(const __nv_bfloat16* __restrict__ Ah, const __nv_bfloat16* __restrict__ Al,
             const __nv_bfloat16* __restrict__ Bh, const __nv_bfloat16* __restrict__ Bl,
             const float* __restrict__ bias, const float* __restrict__ res,
             float* __restrict__ Cf,
             __nv_bfloat16* __restrict__ Ch, __nv_bfloat16* __restrict__ Cl,
             __nv_bfloat16* __restrict__ vth, __nv_bfloat16* __restrict__ vtl,
             int M, int N, int K) {
    constexpr int MI      = BM / 32;
    constexpr int A_TILE  = BM * 128;
    constexpr int B_TILE  = 16384;
    constexpr int STG     = (BM == 128) ? 3 : 2;
    constexpr int STAGE   = 2 * A_TILE + 2 * B_TILE;

    extern __shared__ char dsm[];
    const uint32_t base = smem_u32(dsm);

    const int tid  = threadIdx.x;
    const int wid  = tid >> 5;
    const int lane = tid & 31;
    const int m0 = blockIdx.y * BM;
    const int n0 = blockIdx.x * 128;
    const int wm = wid & 1;
    const int wn = wid >> 1;

    float acc[MI][4][4];
    #pragma unroll
    for (int i = 0; i < MI; i++)
        #pragma unroll
        for (int j = 0; j < 4; j++)
            #pragma unroll
            for (int r = 0; r < 4; r++) acc[i][j][r] = 0.0f;

    const int nkt = K >> 6;

    const int a_row  = wm * (BM / 2) + (lane & 15);
    const int a_csel = lane >> 4;
    const int b_row  = wn * 32 + ((lane & 7) | ((lane & 16) >> 1));
    const int b_csel = (lane >> 3) & 1;

    {
        load_tile_cp<BM>(Ah, m0, K, 0, base, tid);
        load_tile_cp<BM>(Al, m0, K, 0, base + A_TILE, tid);
        load_tile_cp<128>(Bh, n0, K, 0, base + 2 * A_TILE, tid);
        load_tile_cp<128>(Bl, n0, K, 0, base + 2 * A_TILE + B_TILE, tid);
        CP_COMMIT();
        load_tile_cp<BM>(Ah, m0, K, 1, base + STAGE, tid);
        load_tile_cp<BM>(Al, m0, K, 1, base + STAGE + A_TILE, tid);
        load_tile_cp<128>(Bh, n0, K, 1, base + STAGE + 2 * A_TILE, tid);
        load_tile_cp<128>(Bl, n0, K, 1, base + STAGE + 2 * A_TILE + B_TILE, tid);
        CP_COMMIT();
    }

    for (int kt = 0; kt < nkt; kt++) {
        if (kt + 1 < nkt) { CP_WAIT1(); } else { CP_WAIT0(); }
        __syncthreads();

        if (STG == 3 && kt + 2 < nkt) {
            const uint32_t nb = base + ((kt + 2) % 3) * STAGE;
            load_tile_cp<BM>(Ah, m0, K, kt + 2, nb, tid);
            load_tile_cp<BM>(Al, m0, K, kt + 2, nb + A_TILE, tid);
            load_tile_cp<128>(Bh, n0, K, kt + 2, nb + 2 * A_TILE, tid);
            load_tile_cp<128>(Bl, n0, K, kt + 2, nb + 2 * A_TILE + B_TILE, tid);
            CP_COMMIT();
        }

        const uint32_t sb  = base + (kt % STG) * STAGE;
        const uint32_t sAh = sb;
        const uint32_t sAl = sb + A_TILE;
        const uint32_t sBh = sb + 2 * A_TILE;
        const uint32_t sBl = sb + 2 * A_TILE + B_TILE;

        #pragma unroll
        for (int ks = 0; ks < 4; ks++) {
            const int ac = ks * 2 + a_csel;
            const int bc = ks * 2 + b_csel;
            uint32_t bh[4][2], bl[4][2];
            #pragma unroll
            for (int nj = 0; nj < 2; nj++) {
                int row = b_row + nj * 16;
                ldm_x4(sBh + SWZ(row, bc), bh[nj*2][0], bh[nj*2][1], bh[nj*2+1][0], bh[nj*2+1][1]);
                ldm_x4(sBl + SWZ(row, bc), bl[nj*2][0], bl[nj*2][1], bl[nj*2+1][0], bl[nj*2+1][1]);
            }
            #pragma unroll
            for (int mi = 0; mi < MI; mi++) {
                uint32_t ah0, ah1, ah2, ah3, al0, al1, al2, al3;
                int row = a_row + mi * 16;
                ldm_x4(sAh + SWZ(row, ac), ah0, ah1, ah2, ah3);
                ldm_x4(sAl + SWZ(row, ac), al0, al1, al2, al3);
                #pragma unroll
                for (int ni = 0; ni < 4; ni++) {
                    mma_bf16(acc[mi][ni][0], acc[mi][ni][1], acc[mi][ni][2], acc[mi][ni][3],
                             ah0, ah1, ah2, ah3, bh[ni][0], bh[ni][1]);
                    mma_bf16(acc[mi][ni][0], acc[mi][ni][1], acc[mi][ni][2], acc[mi][ni][3],
                             ah0, ah1, ah2, ah3, bl[ni][0], bl[ni][1]);
                    mma_bf16(acc[mi][ni][0], acc[mi][ni][1], acc[mi][ni][2], acc[mi][ni][3],
                             al0, al1, al2, al3, bh[ni][0], bh[ni][1]);
                }
            }
        }

        if (STG == 2) {
            __syncthreads();
            if (kt + 2 < nkt) {
                const uint32_t nb = base + (kt & 1) * STAGE;
                load_tile_cp<BM>(Ah, m0, K, kt + 2, nb, tid);
                load_tile_cp<BM>(Al, m0, K, kt + 2, nb + A_TILE, tid);
                load_tile_cp<128>(Bh, n0, K, kt + 2, nb + 2 * A_TILE, tid);
                load_tile_cp<128>(Bl, n0, K, kt + 2, nb + 2 * A_TILE + B_TILE, tid);
                CP_COMMIT();
            }
        }
    }

    const int qm = lane >> 2;
    const int qn = (lane & 3) * 2;
    const bool vblock = VFUSE && (n0 >= 2 * C_);
    #pragma unroll
    for (int mi = 0; mi < MI; mi++) {
        #pragma unroll
        for (int ni = 0; ni < 4; ni++) {
            const int n = n0 + wn * 32 + ni * 8 + qn;
            float2 bv = *(const float2*)(bias + n);
            #pragma unroll
            for (int half = 0; half < 2; half++) {
                const int m = m0 + wm * (BM / 2) + mi * 16 + qm + half * 8;
                float vx = acc[mi][ni][half*2 + 0] + bv.x;
                float vy = acc[mi][ni][half*2 + 1] + bv.y;
                if (RELU) { vx = fmaxf(vx, 0.f); vy = fmaxf(vy, 0.f); }
                if (RES) {
                    float2 rv = *(const float2*)(res + (size_t)m * N + n);
                    vx += rv.x; vy += rv.y;
                }
                if (vblock) {
                    const int t  = m & (T_ - 1);
                    const int bb = m >> 11;
                    const int nv = n - 2 * C_;
                    const int hh = nv >> 6;
                    const int d  = nv & 63;
                    __nv_bfloat16 h0, l0, h1, l1;
                    split1(vx, h0, l0);
                    split1(vy, h1, l1);
                    size_t vo = ((size_t)(bb * H_ + hh) * 64 + d) * T_ + t;
                    vth[vo]      = h0;
                    vth[vo + T_] = h1;
                    vtl[vo]      = l0;
                    vtl[vo + T_] = l1;
                } else if (OUTBF16) {
                    split2_store(vx, vy, Ch + (size_t)m * N + n, Cl + (size_t)m * N + n);
                } else {
                    *(float2*)(Cf + (size_t)m * N + n) = make_float2(vx, vy);
                }
            }
        }
    }
}

// ===========================================================================
// Tensor-core flash attention (64 queries/CTA, 4 warps).
// Softmax in base-2 domain: scores scaled by 0.125*log2(e), exp2f throughout.
// ===========================================================================
#define ATT_SMEM (16384 + 32768)
#define SCALE_LOG2E 0.18033688f   // 0.125 * log2(e)

__global__ __launch_bounds__(128)
void attention_mma_kernel(const __nv_bfloat16* __restrict__ qkvh,
                          const __nv_bfloat16* __restrict__ qkvl,
                          const __nv_bfloat16* __restrict__ Vth,
                          const __nv_bfloat16* __restrict__ Vtl,
                          __nv_bfloat16* __restrict__ aoh,
                          __nv_bfloat16* __restrict__ aol) {
    extern __shared__ char dsm[];
    const uint32_t base = smem_u32(dsm);
    const uint32_t sQh = base;
    const uint32_t sQl = base + 8192;
    const uint32_t sKh = base + 16384;
    const uint32_t sKl = base + 24576;
    const uint32_t sVh = base + 32768;
    const uint32_t sVl = base + 40960;

    const int b  = blockIdx.z;
    const int h  = blockIdx.y;
    const int qt = (T_ / 64 - 1) - blockIdx.x;
    const int tid  = threadIdx.x;
    const int wid  = tid >> 5;
    const int lane = tid & 31;
    const int m_base = wid * 16;

    #pragma unroll
    for (int r = 0; r < 4; r++) {
        int cid = tid + r * 128;
        int row = cid >> 3;
        int c   = cid & 7;
        size_t goff = (size_t)(b * T_ + qt * 64 + row) * QKV_ + h * 64 + c * 8;
        CP_ASYNC16(sQh + SWZ(row, c), qkvh + goff);
        CP_ASYNC16(sQl + SWZ(row, c), qkvl + goff);
    }
    CP_COMMIT(); CP_WAIT0();
    __syncthreads();

    const int a_row  = m_base + (lane & 15);
    const int a_csel = lane >> 4;
    uint32_t qfh[4][4], qfl[4][4];
    #pragma unroll
    for (int ks = 0; ks < 4; ks++) {
        ldm_x4(sQh + SWZ(a_row, ks*2 + a_csel), qfh[ks][0], qfh[ks][1], qfh[ks][2], qfh[ks][3]);
        ldm_x4(sQl + SWZ(a_row, ks*2 + a_csel), qfl[ks][0], qfl[ks][1], qfl[ks][2], qfl[ks][3]);
    }

    const int b_row_l = (lane & 7) | ((lane & 16) >> 1);
    const int b_csel  = (lane >> 3) & 1;
    const int qm = lane >> 2;
    const int qn = (lane & 3) * 2;

    float o[8][4];
    #pragma unroll
    for (int n = 0; n < 8; n++)
        #pragma unroll
        for (int r = 0; r < 4; r++) o[n][r] = 0.0f;
    float mrow[2] = {-FLT_MAX, -FLT_MAX};
    float lrow[2] = {0.0f, 0.0f};

    for (int kt = 0; kt <= qt; kt++) {
        __syncthreads();
        #pragma unroll
        for (int r = 0; r < 4; r++) {
            int cid = tid + r * 128;
            int row = cid >> 3;
            int c   = cid & 7;
            size_t koff = (size_t)(b * T_ + kt * 64 + row) * QKV_ + C_ + h * 64 + c * 8;
            size_t voff = ((size_t)(b * H_ + h) * 64 + row) * T_ + kt * 64 + c * 8;
            CP_ASYNC16(sKh + SWZ(row, c), qkvh + koff);
            CP_ASYNC16(sKl + SWZ(row, c), qkvl + koff);
            CP_ASYNC16(sVh + SWZ(row, c), Vth + voff);
            CP_ASYNC16(sVl + SWZ(row, c), Vtl + voff);
        }
        CP_COMMIT(); CP_WAIT0();
        __syncthreads();

        float sc[8][4];
        #pragma unroll
        for (int n = 0; n < 8; n++)
            #pragma unroll
            for (int r = 0; r < 4; r++) sc[n][r] = 0.0f;

        #pragma unroll
        for (int ks = 0; ks < 4; ks++) {
            const int bc = ks * 2 + b_csel;
            #pragma unroll
            for (int g = 0; g < 4; g++) {
                uint32_t r0, r1, r2, r3, s0, s1, s2, s3;
                ldm_x4(sKh + SWZ(g * 16 + b_row_l, bc), r0, r1, r2, r3);
                ldm_x4(sKl + SWZ(g * 16 + b_row_l, bc), s0, s1, s2, s3);
                mma_bf16(sc[2*g][0], sc[2*g][1], sc[2*g][2], sc[2*g][3],
                         qfh[ks][0], qfh[ks][1], qfh[ks][2], qfh[ks][3], r0, r1);
                mma_bf16(sc[2*g+1][0], sc[2*g+1][1], sc[2*g+1][2], sc[2*g+1][3],
                         qfh[ks][0], qfh[ks][1], qfh[ks][2], qfh[ks][3], r2, r3);
                mma_bf16(sc[2*g][0], sc[2*g][1], sc[2*g][2], sc[2*g][3],
                         qfh[ks][0], qfh[ks][1], qfh[ks][2], qfh[ks][3], s0, s1);
                mma_bf16(sc[2*g+1][0], sc[2*g+1][1], sc[2*g+1][2], sc[2*g+1][3],
                         qfh[ks][0], qfh[ks][1], qfh[ks][2], qfh[ks][3], s2, s3);
                mma_bf16(sc[2*g][0], sc[2*g][1], sc[2*g][2], sc[2*g][3],
                         qfl[ks][0], qfl[ks][1], qfl[ks][2], qfl[ks][3], r0, r1);
                mma_bf16(sc[2*g+1][0], sc[2*g+1][1], sc[2*g+1][2], sc[2*g+1][3],
                         qfl[ks][0], qfl[ks][1], qfl[ks][2], qfl[ks][3], r2, r3);
            }
        }

        // scale into base-2 softmax domain (0.125 * log2 e)
        #pragma unroll
        for (int n = 0; n < 8; n++)
            #pragma unroll
            for (int r = 0; r < 4; r++) sc[n][r] *= SCALE_LOG2E;

        if (kt == qt) {
            const int row0 = m_base + qm;
            const int row1 = row0 + 8;
            #pragma unroll
            for (int n = 0; n < 8; n++) {
                int col = n * 8 + qn;
                if (col     > row0) sc[n][0] = -FLT_MAX;
                if (col + 1 > row0) sc[n][1] = -FLT_MAX;
                if (col     > row1) sc[n][2] = -FLT_MAX;
                if (col + 1 > row1) sc[n][3] = -FLT_MAX;
            }
        }

        #pragma unroll
        for (int r = 0; r < 2; r++) {
            float mx = -FLT_MAX;
            #pragma unroll
            for (int n = 0; n < 8; n++) {
                mx = fmaxf(mx, sc[n][2*r]);
                mx = fmaxf(mx, sc[n][2*r + 1]);
            }
            mx = fmaxf(mx, __shfl_xor_sync(0xffffffffu, mx, 1));
            mx = fmaxf(mx, __shfl_xor_sync(0xffffffffu, mx, 2));
            float mnew = fmaxf(mrow[r], mx);
            float alpha = exp2f(mrow[r] - mnew);
            float sum = 0.0f;
            #pragma unroll
            for (int n = 0; n < 8; n++) {
                float p0 = exp2f(sc[n][2*r]     - mnew);
                float p1 = exp2f(sc[n][2*r + 1] - mnew);
                sc[n][2*r]     = p0;
                sc[n][2*r + 1] = p1;
                sum += p0 + p1;
            }
            sum += __shfl_xor_sync(0xffffffffu, sum, 1);
            sum += __shfl_xor_sync(0xffffffffu, sum, 2);
            lrow[r] = lrow[r] * alpha + sum;
            mrow[r] = mnew;
            #pragma unroll
            for (int n = 0; n < 8; n++) {
                o[n][2*r]     *= alpha;
                o[n][2*r + 1] *= alpha;
            }
        }

        #pragma unroll
        for (int ks = 0; ks < 4; ks++) {
            uint32_t ph0, ph1, ph2, ph3, pl0, pl1, pl2, pl3;
            pack_split(sc[2*ks][0],   sc[2*ks][1],   ph0, pl0);
            pack_split(sc[2*ks][2],   sc[2*ks][3],   ph1, pl1);
            pack_split(sc[2*ks+1][0], sc[2*ks+1][1], ph2, pl2);
            pack_split(sc[2*ks+1][2], sc[2*ks+1][3], ph3, pl3);
            const int bc = ks * 2 + b_csel;
            #pragma unroll
            for (int g = 0; g < 4; g++) {
                uint32_t r0, r1, r2, r3, s0, s1, s2, s3;
                ldm_x4(sVh + SWZ(g * 16 + b_row_l, bc), r0, r1, r2, r3);
                ldm_x4(sVl + SWZ(g * 16 + b_row_l, bc), s0, s1, s2, s3);
                mma_bf16(o[2*g][0], o[2*g][1], o[2*g][2], o[2*g][3],
                         ph0, ph1, ph2, ph3, r0, r1);
                mma_bf16(o[2*g+1][0], o[2*g+1][1], o[2*g+1][2], o[2*g+1][3],
                         ph0, ph1, ph2, ph3, r2, r3);
                mma_bf16(o[2*g][0], o[2*g][1], o[2*g][2], o[2*g][3],
                         ph0, ph1, ph2, ph3, s0, s1);
                mma_bf16(o[2*g+1][0], o[2*g+1][1], o[2*g+1][2], o[2*g+1][3],
                         ph0, ph1, ph2, ph3, s2, s3);
                mma_bf16(o[2*g][0], o[2*g][1], o[2*g][2], o[2*g][3],
                         pl0, pl1, pl2, pl3, r0, r1);
                mma_bf16(o[2*g+1][0], o[2*g+1][1], o[2*g+1][2], o[2*g+1][3],
                         pl0, pl1, pl2, pl3, r2, r3);
            }
        }
    }

    const float inv0 = 1.0f / lrow[0];
    const float inv1 = 1.0f / lrow[1];
    const size_t row0 = (size_t)(b * T_ + qt * 64 + m_base + qm) * C_;
    const size_t row1 = row0 + 8 * C_;
    #pragma unroll
    for (int n = 0; n < 8; n++) {
        int col = h * 64 + n * 8 + qn;
        split2_store(o[n][0] * inv0, o[n][1] * inv0, aoh + row0 + col, aol + row0 + col);
        split2_store(o[n][2] * inv1, o[n][3] * inv1, aoh + row1 + col, aol + row1 + col);
    }
}

// ===========================================================================
// Logits (per-batch blocks, R8 version)
// ===========================================================================
__global__ void logits_kernel(const float* __restrict__ xf,
                              const float* __restrict__ W,
                              const float* __restrict__ bias,
                              float* __restrict__ out) {
    __shared__ float xs[C_];
    const int b = blockIdx.y;
    const int tid = threadIdx.x;
    #pragma unroll
    for (int r = 0; r < C_ / 128; r++)
        xs[tid + r * 128] = xf[b * C_ + tid + r * 128];
    __syncthreads();

    int vcol = blockIdx.x * 128 + tid;
    float acc = bias[vcol];
    const float* wp = W + vcol;
    #pragma unroll 8
    for (int k = 0; k < C_; k++)
        acc = fmaf(xs[k], wp[(size_t)k * V_], acc);
    out[(size_t)b * V_ + vcol] = acc;
}

// ===========================================================================
// Launch (R8 structure exactly)
// ===========================================================================
extern "C" void kernel_launch(void* const* d_in, const int* in_sizes, int n_in,
                              void* d_out, int out_size) {
    const int*   idx   = (const int*)  d_in[0];
    const float* emb   = (const float*)d_in[1];
    const float* pos   = (const float*)d_in[2];
    const float* ln1_g = (const float*)d_in[3];
    const float* ln1_b = (const float*)d_in[4];
    const float* wq    = (const float*)d_in[5];
    const float* bq    = (const float*)d_in[6];
    const float* wk    = (const float*)d_in[7];
    const float* bk    = (const float*)d_in[8];
    const float* wv    = (const float*)d_in[9];
    const float* bv    = (const float*)d_in[10];
    const float* wo    = (const float*)d_in[11];
    const float* bo    = (const float*)d_in[12];
    const float* ln2_g = (const float*)d_in[13];
    const float* ln2_b = (const float*)d_in[14];
    const float* w1    = (const float*)d_in[15];
    const float* b1    = (const float*)d_in[16];
    const float* w2    = (const float*)d_in[17];
    const float* b2    = (const float*)d_in[18];
    const float* lnf_g = (const float*)d_in[19];
    const float* lnf_b = (const float*)d_in[20];
    const float* out_w = (const float*)d_in[21];
    const float* out_b = (const float*)d_in[22];
    float* out = (float*)d_out;

    float *x, *xf, *bqkv;
    cudaGetSymbolAddress((void**)&x,    g_x);
    cudaGetSymbolAddress((void**)&xf,   g_xf);
    cudaGetSymbolAddress((void**)&bqkv, g_bqkv);

    __nv_bfloat16 *h_h, *h_l, *qkvh, *qkvl, *vth, *vtl, *ao_h, *ao_l, *hid_h, *hid_l;
    cudaGetSymbolAddress((void**)&h_h,   g_h_h);
    cudaGetSymbolAddress((void**)&h_l,   g_h_l);
    cudaGetSymbolAddress((void**)&qkvh,  g_qkvh);
    cudaGetSymbolAddress((void**)&qkvl,  g_qkvl);
    cudaGetSymbolAddress((void**)&vth,   g_vth);
    cudaGetSymbolAddress((void**)&vtl,   g_vtl);
    cudaGetSymbolAddress((void**)&ao_h,  g_ao_h);
    cudaGetSymbolAddress((void**)&ao_l,  g_ao_l);
    cudaGetSymbolAddress((void**)&hid_h, g_hid_h);
    cudaGetSymbolAddress((void**)&hid_l, g_hid_l);

    __nv_bfloat16 *wqkvT_h, *wqkvT_l, *woT_h, *woT_l, *w1T_h, *w1T_l, *w2T_h, *w2T_l;
    cudaGetSymbolAddress((void**)&wqkvT_h, g_wqkvT_h);
    cudaGetSymbolAddress((void**)&wqkvT_l, g_wqkvT_l);
    cudaGetSymbolAddress((void**)&woT_h, g_woT_h);
    cudaGetSymbolAddress((void**)&woT_l, g_woT_l);
    cudaGetSymbolAddress((void**)&w1T_h, g_w1T_h);
    cudaGetSymbolAddress((void**)&w1T_l, g_w1T_l);
    cudaGetSymbolAddress((void**)&w2T_h, g_w2T_h);
    cudaGetSymbolAddress((void**)&w2T_l, g_w2T_l);

    cudaFuncSetAttribute(gemm_tc<256, false, false, true, true>,
                         cudaFuncAttributeMaxDynamicSharedMemorySize, GEMM_SMEM);
    cudaFuncSetAttribute(gemm_tc<128, true, false, true, false>,
                         cudaFuncAttributeMaxDynamicSharedMemorySize, GEMM_SMEM);
    cudaFuncSetAttribute(gemm_tc<256, false, true, false, false>,
                         cudaFuncAttributeMaxDynamicSharedMemorySize, GEMM_SMEM);
    cudaFuncSetAttribute(attention_mma_kernel,
                         cudaFuncAttributeMaxDynamicSharedMemorySize, ATT_SMEM);

    // Weight prep: 3 launches
    {
        dim3 blk(32, 8);
        transpose_split_qkv_kernel<<<dim3(32, 32, 24), blk>>>(wq, wk, wv, wqkvT_h, wqkvT_l);
        transpose_split_wo_w2_kernel<<<dim3(32, 160, 8), blk>>>(wo, w2, woT_h, woT_l, w2T_h, w2T_l);
        transpose_split_kernel<<<dim3(128, 32, 8), blk>>>(w1, w1T_h, w1T_l, C_, F_, (size_t)C_ * F_);
    }

    embed_kernel<<<BT_, 256>>>(idx, emb, pos, bq, bk, bv, x, bqkv);

    dim3 gemm_qkv(QKV_ / 128, BT_ / 256);  // (24, 16)  BM=256, V fused-transposed
    dim3 gemm_cc(C_ / 128, BT_ / 256);     // (8, 16)   BM=256
    dim3 gemm_cf(F_ / 128, BT_ / 128);     // (32, 32)  BM=128
    dim3 attn_grid(T_ / 64, H_, B_);

    for (int l = 0; l < L_; l++) {
        layernorm_bf16_kernel<<<BT_, 256>>>(x, ln1_g + l * C_, ln1_b + l * C_, h_h, h_l);

        // merged QKV projection; V columns written straight into vt layout
        gemm_tc<256, false, false, true, true><<<gemm_qkv, 256, GEMM_SMEM>>>(
            h_h, h_l, wqkvT_h + (size_t)l * QKV_ * C_, wqkvT_l + (size_t)l * QKV_ * C_,
            bqkv + l * QKV_, nullptr, nullptr, qkvh, qkvl, vth, vtl, BT_, QKV_, C_);

        attention_mma_kernel<<<attn_grid, 128, ATT_SMEM>>>(
            qkvh, qkvl, vth, vtl, ao_h, ao_l);

        // x = x + (ao @ wo + bo)
        gemm_tc<256, false, true, false, false><<<gemm_cc, 256, GEMM_SMEM>>>(
            ao_h, ao_l, woT_h + (size_t)l * C_ * C_, woT_l + (size_t)l * C_ * C_,
            bo + l * C_, x, x, nullptr, nullptr, nullptr, nullptr, BT_, C_, C_);

        layernorm_bf16_kernel<<<BT_, 256>>>(x, ln2_g + l * C_, ln2_b + l * C_, h_h, h_l);

        // hid = relu(h @ w1 + b1)
        gemm_tc<128, true, false, true, false><<<gemm_cf, 256, GEMM_SMEM>>>(
            h_h, h_l, w1T_h + (size_t)l * C_ * F_, w1T_l + (size_t)l * C_ * F_,
            b1 + l * F_, nullptr, nullptr, hid_h, hid_l, nullptr, nullptr, BT_, F_, C_);
        // x = x + (hid @ w2 + b2)
        gemm_tc<256, false, true, false, false><<<gemm_cc, 256, GEMM_SMEM>>>(
            hid_h, hid_l, w2T_h + (size_t)l * F_ * C_, w2T_l + (size_t)l * F_ * C_,
            b2 + l * C_, x, x, nullptr, nullptr, nullptr, nullptr, BT_, C_, F_);
    }

    layernorm_last_kernel<<<B_, 256>>>(x, lnf_g, lnf_b, xf);
    logits_kernel<<<dim3(V_ / 128, B_), 128>>>(xf, out_w, out_b, out);
}